// round 5
// baseline (speedup 1.0000x reference)
#include <cuda_runtime.h>
#include <cuda_bf16.h>
#include <cstdint>

#define NRES 384
#define CH 128
#define NN (NRES*NRES)
#define EPSF 1e-5f
#define KSPLIT (3*NRES)   // 1152

// ---- scratch (device globals; no allocation) ----
__device__ __nv_bfloat16 g_as[(size_t)CH*NRES*KSPLIT]; // A' per h: [i][k'] = [hi|lo|hi]
__device__ __nv_bfloat16 g_bs[(size_t)CH*NRES*KSPLIT]; // B' per h: [j][k'] = [hi|hi|lo]
__device__ float g_gate[(size_t)NN*CH];
__device__ float g_xt[(size_t)CH*NN];
__device__ float g_wT[6*CH*CH];

__device__ __forceinline__ float sigf(float x){ return 1.f/(1.f+__expf(-x)); }

// ---- mma.sync helpers (baseline PTX, valid on plain sm_103) ----
__device__ __forceinline__ uint32_t s2u(const void* p){
    uint32_t a;
    asm("{ .reg .u64 t; cvta.to.shared.u64 t, %1; cvt.u32.u64 %0, t; }" : "=r"(a) : "l"(p));
    return a;
}
__device__ __forceinline__ void ldsm4(uint32_t &r0,uint32_t &r1,uint32_t &r2,uint32_t &r3,uint32_t a){
    asm volatile("ldmatrix.sync.aligned.m8n8.x4.shared.b16 {%0,%1,%2,%3}, [%4];"
        : "=r"(r0),"=r"(r1),"=r"(r2),"=r"(r3) : "r"(a));
}
__device__ __forceinline__ void mma16816(float* d, const uint32_t* a, const uint32_t* b){
    asm volatile("mma.sync.aligned.m16n8k16.row.col.f32.bf16.bf16.f32 "
        "{%0,%1,%2,%3}, {%4,%5,%6,%7}, {%8,%9}, {%0,%1,%2,%3};"
        : "+f"(d[0]),"+f"(d[1]),"+f"(d[2]),"+f"(d[3])
        : "r"(a[0]),"r"(a[1]),"r"(a[2]),"r"(a[3]), "r"(b[0]),"r"(b[1]));
}

// ---- all 6 weight transposes in one launch ----
__global__ void transpose_all(const float* s0, const float* s1, const float* s2,
                              const float* s3, const float* s4, const float* s5){
    __shared__ float t[32][33];
    const float* srcs[6] = {s0,s1,s2,s3,s4,s5};
    int idx = blockIdx.z;
    const float* src = srcs[idx];
    float* dst = g_wT + idx*CH*CH;
    int x0=blockIdx.x*32, y0=blockIdx.y*32;
    int tx=threadIdx.x, ty=threadIdx.y;
    #pragma unroll
    for (int j=0;j<32;j+=8) t[ty+j][tx] = src[(y0+ty+j)*CH + x0+tx];
    __syncthreads();
    #pragma unroll
    for (int j=0;j<32;j+=8) dst[(x0+ty+j)*CH + y0+tx] = t[tx][ty+j];
}

// ---- fused LN + 5 GEMMs + gated epilogues; 32 rows/block ----
__global__ __launch_bounds__(256)
void proj_kernel(const float* __restrict__ z, const float* __restrict__ mask,
                 const float* __restrict__ lnw, const float* __restrict__ lnb,
                 const float* __restrict__ agb, const float* __restrict__ apb,
                 const float* __restrict__ bgb, const float* __restrict__ bpb,
                 const float* __restrict__ gb)
{
    __shared__ float z_s[32*132];
    __shared__ float wg_s[8*132];
    __shared__ float wp_s[8*132];
    __shared__ float ot[128*34];
    int tid = threadIdx.x;
    int row0 = blockIdx.x*32;

    const float4* z4 = (const float4*)(z + (size_t)row0*CH);
    #pragma unroll
    for (int it=0; it<4; ++it){
        int f = tid + it*256;
        int r = f>>5, c4 = f&31;
        *(float4*)(z_s + r*132 + c4*4) = z4[f];
    }
    __syncthreads();

    int lane = tid&31, wid = tid>>5;
    #pragma unroll
    for (int rr=0; rr<4; ++rr){
        int r = wid*4+rr;
        float v[4], s=0.f, q=0.f;
        #pragma unroll
        for (int m=0;m<4;++m){ float x=z_s[r*132+lane+32*m]; v[m]=x; s+=x; q+=x*x; }
        #pragma unroll
        for (int o=16;o>0;o>>=1){ s+=__shfl_xor_sync(0xffffffffu,s,o); q+=__shfl_xor_sync(0xffffffffu,q,o); }
        float mu=s*(1.f/128.f), var=q*(1.f/128.f)-mu*mu;
        float rs=rsqrtf(fmaxf(var,0.f)+EPSF);
        #pragma unroll
        for (int m=0;m<4;++m){
            int c=lane+32*m;
            z_s[r*132+c] = (v[m]-mu)*rs*lnw[c]+lnb[c];
        }
    }
    __syncthreads();

    int tx = tid&15, ty = tid>>4;
    const float* WgT[3] = {g_wT, g_wT+2*CH*CH, g_wT+4*CH*CH};
    const float* WpT[3] = {g_wT+CH*CH, g_wT+3*CH*CH, 0};
    const float* GB[3]  = {agb, bgb, gb};
    const float* PB[3]  = {apb, bpb, 0};

    for (int ph=0; ph<3; ++ph){
        bool hasP = (ph<2);
        float accg[2][8], accp[2][8];
        #pragma unroll
        for (int u=0;u<2;++u)
            #pragma unroll
            for (int v=0;v<8;++v){ accg[u][v]=0.f; accp[u][v]=0.f; }

        for (int c0=0;c0<CH;c0+=8){
            int c=tid>>5, o4=tid&31;
            *(float4*)(wg_s + c*132 + o4*4) = *(const float4*)(WgT[ph] + (c0+c)*CH + o4*4);
            if (hasP)
                *(float4*)(wp_s + c*132 + o4*4) = *(const float4*)(WpT[ph] + (c0+c)*CH + o4*4);
            __syncthreads();
            #pragma unroll
            for (int i=0;i<8;++i){
                float z0 = z_s[(ty*2+0)*132 + c0+i];
                float z1 = z_s[(ty*2+1)*132 + c0+i];
                float4 wa = *(float4*)(wg_s + i*132 + tx*8);
                float4 wb = *(float4*)(wg_s + i*132 + tx*8 + 4);
                accg[0][0]+=z0*wa.x; accg[0][1]+=z0*wa.y; accg[0][2]+=z0*wa.z; accg[0][3]+=z0*wa.w;
                accg[0][4]+=z0*wb.x; accg[0][5]+=z0*wb.y; accg[0][6]+=z0*wb.z; accg[0][7]+=z0*wb.w;
                accg[1][0]+=z1*wa.x; accg[1][1]+=z1*wa.y; accg[1][2]+=z1*wa.z; accg[1][3]+=z1*wa.w;
                accg[1][4]+=z1*wb.x; accg[1][5]+=z1*wb.y; accg[1][6]+=z1*wb.z; accg[1][7]+=z1*wb.w;
                if (hasP){
                    float4 pa = *(float4*)(wp_s + i*132 + tx*8);
                    float4 pb4= *(float4*)(wp_s + i*132 + tx*8 + 4);
                    accp[0][0]+=z0*pa.x; accp[0][1]+=z0*pa.y; accp[0][2]+=z0*pa.z; accp[0][3]+=z0*pa.w;
                    accp[0][4]+=z0*pb4.x; accp[0][5]+=z0*pb4.y; accp[0][6]+=z0*pb4.z; accp[0][7]+=z0*pb4.w;
                    accp[1][0]+=z1*pa.x; accp[1][1]+=z1*pa.y; accp[1][2]+=z1*pa.z; accp[1][3]+=z1*pa.w;
                    accp[1][4]+=z1*pb4.x; accp[1][5]+=z1*pb4.y; accp[1][6]+=z1*pb4.z; accp[1][7]+=z1*pb4.w;
                }
            }
            __syncthreads();
        }

        if (hasP){
            __nv_bfloat16* dstS = ph ? g_bs : g_as;
            #pragma unroll
            for (int u=0;u<2;++u){
                int r = ty*2+u;
                float mk = mask[row0+r];
                #pragma unroll
                for (int v=0;v<8;++v){
                    int o = tx*8+v;
                    ot[o*34 + r] = mk * sigf(accg[u][v]+GB[ph][o]) * (accp[u][v]+PB[ph][o]);
                }
            }
            __syncthreads();
            int irow = row0 / NRES;
            int k0   = row0 % NRES;
            #pragma unroll
            for (int it=0; it<16; ++it){
                int f = tid + it*256;
                int r=f&31, o=f>>5;
                float v = ot[o*34+r];
                __nv_bfloat16 hi = __float2bfloat16(v);
                __nv_bfloat16 lo = __float2bfloat16(v - __bfloat162float(hi));
                size_t base = (size_t)o*(NRES*KSPLIT) + (size_t)irow*KSPLIT + k0 + r;
                if (ph==0){ // A' = [hi | lo | hi]
                    dstS[base]          = hi;
                    dstS[base +   NRES] = lo;
                    dstS[base + 2*NRES] = hi;
                } else {    // B' = [hi | hi | lo]
                    dstS[base]          = hi;
                    dstS[base +   NRES] = hi;
                    dstS[base + 2*NRES] = lo;
                }
            }
            __syncthreads();
        } else {
            #pragma unroll
            for (int u=0;u<2;++u){
                int grow = row0 + ty*2+u;
                #pragma unroll
                for (int v=0;v<8;++v){
                    int o=tx*8+v;
                    g_gate[(size_t)grow*CH + o] = sigf(accg[u][v]+gb[o]);
                }
            }
        }
    }
}

// ---- triangle GEMM on mma.sync bf16: per (h,i-tile,j-tile) D[128x128]=A'·B'^T, K'=1152 ----
#define BK 32
#define LDA 40          // bf16 units per smem row (80B: conflict-free ldmatrix phases)
#define NCH (KSPLIT/BK) // 36

__global__ __launch_bounds__(256)
void tri_mma_kernel(){
    __shared__ __nv_bfloat16 As[2][128*LDA];
    __shared__ __nv_bfloat16 Bs[2][128*LDA];

    int tid = threadIdx.x;
    int wid = tid>>5, lane = tid&31;
    int wm = wid & 1, wn = wid >> 1;      // 2 x 4 warp grid: 64 x 32 per warp
    int h = blockIdx.z, i0 = blockIdx.y*128, j0 = blockIdx.x*128;

    const __nv_bfloat16* Ag = g_as + ((size_t)h*NRES + i0)*KSPLIT;
    const __nv_bfloat16* Bg = g_bs + ((size_t)h*NRES + j0)*KSPLIT;

    float acc[4][4][4];
    #pragma unroll
    for (int mf=0;mf<4;++mf)
        #pragma unroll
        for (int nf=0;nf<4;++nf)
            #pragma unroll
            for (int r=0;r<4;++r) acc[mf][nf][r]=0.f;

    int lrow = tid>>2, lsub = tid&3;      // 256 threads: 64 rows x 4 x 16B per pass

    // prefetch chunk 0
    #pragma unroll
    for (int half=0; half<2; ++half){
        int row = lrow + half*64;
        *(uint4*)(&As[0][row*LDA + lsub*8]) = *(const uint4*)(Ag + (size_t)row*KSPLIT + lsub*8);
        *(uint4*)(&Bs[0][row*LDA + lsub*8]) = *(const uint4*)(Bg + (size_t)row*KSPLIT + lsub*8);
    }
    __syncthreads();

    for (int c=0; c<NCH; ++c){
        int buf = c & 1;
        // issue next-chunk global loads early
        uint4 pa[2], pb[2];
        if (c+1 < NCH){
            #pragma unroll
            for (int half=0; half<2; ++half){
                int row = lrow + half*64;
                pa[half] = *(const uint4*)(Ag + (size_t)row*KSPLIT + (c+1)*BK + lsub*8);
                pb[half] = *(const uint4*)(Bg + (size_t)row*KSPLIT + (c+1)*BK + lsub*8);
            }
        }
        uint32_t as_base = s2u(&As[buf][0]);
        uint32_t bs_base = s2u(&Bs[buf][0]);
        #pragma unroll
        for (int ks=0; ks<2; ++ks){
            uint32_t a[4][4];
            #pragma unroll
            for (int mf=0; mf<4; ++mf){
                int row = wm*64 + mf*16 + (lane&15);
                int kc  = ks*16 + (lane>>4)*8;
                ldsm4(a[mf][0],a[mf][1],a[mf][2],a[mf][3], as_base + (row*LDA + kc)*2);
            }
            uint32_t b[4][2];
            #pragma unroll
            for (int nf2=0; nf2<2; ++nf2){
                int nrow = wn*32 + nf2*16 + (lane&7) + ((lane>>4)<<3);
                int kc   = ks*16 + ((lane>>3)&1)*8;
                uint32_t r0,r1,r2,r3;
                ldsm4(r0,r1,r2,r3, bs_base + (nrow*LDA + kc)*2);
                b[nf2*2+0][0]=r0; b[nf2*2+0][1]=r1;
                b[nf2*2+1][0]=r2; b[nf2*2+1][1]=r3;
            }
            #pragma unroll
            for (int mf=0; mf<4; ++mf)
                #pragma unroll
                for (int nf=0; nf<4; ++nf)
                    mma16816(acc[mf][nf], a[mf], b[nf]);
        }
        if (c+1 < NCH){
            int nbuf = buf^1;
            #pragma unroll
            for (int half=0; half<2; ++half){
                int row = lrow + half*64;
                *(uint4*)(&As[nbuf][row*LDA + lsub*8]) = pa[half];
                *(uint4*)(&Bs[nbuf][row*LDA + lsub*8]) = pb[half];
            }
        }
        __syncthreads();
    }

    // epilogue: acc -> g_xt (fp32)
    float* X = g_xt + (size_t)h*NN;
    #pragma unroll
    for (int mf=0; mf<4; ++mf){
        #pragma unroll
        for (int nf=0; nf<4; ++nf){
            int row = i0 + wm*64 + mf*16 + (lane>>2);
            int col = j0 + wn*32 + nf*8 + (lane&3)*2;
            *(float2*)(X + (size_t)row*NRES + col)     = make_float2(acc[mf][nf][0], acc[mf][nf][1]);
            *(float2*)(X + (size_t)(row+8)*NRES + col) = make_float2(acc[mf][nf][2], acc[mf][nf][3]);
        }
    }
}

// ---- LN over h + output GEMM + gate; 64 rows/block ----
__global__ __launch_bounds__(256)
void out_kernel(const float* __restrict__ low, const float* __restrict__ lob,
                const float* __restrict__ zb, float* __restrict__ out)
{
    __shared__ float xs[128*66];
    __shared__ float zw_s[16*132];
    __shared__ float mu_s[64], rs_s[64];
    __shared__ float low_s[128], lob_s[128];
    int tid=threadIdx.x;
    int row0 = blockIdx.x*64;
    if (tid<128){ low_s[tid]=low[tid]; lob_s[tid]=lob[tid]; }
    #pragma unroll
    for (int it=0; it<32; ++it){
        int f = tid + it*256;
        int r = f&63, h = f>>6;
        xs[h*66 + r] = g_xt[(size_t)h*NN + row0 + r];
    }
    __syncthreads();
    int lane=tid&31, wid=tid>>5;
    #pragma unroll
    for (int rr=0;rr<8;++rr){
        int r = wid*8+rr;
        float s=0.f,q=0.f;
        #pragma unroll
        for (int m=0;m<4;++m){ float x=xs[(lane+32*m)*66 + r]; s+=x; q+=x*x; }
        #pragma unroll
        for (int o=16;o>0;o>>=1){ s+=__shfl_xor_sync(0xffffffffu,s,o); q+=__shfl_xor_sync(0xffffffffu,q,o); }
        if (lane==0){
            float mu=s*(1.f/128.f), var=q*(1.f/128.f)-mu*mu;
            mu_s[r]=mu; rs_s[r]=rsqrtf(fmaxf(var,0.f)+EPSF);
        }
    }
    __syncthreads();
    int tx=tid&15, ty=tid>>4;
    float acc[4][8];
    #pragma unroll
    for (int u=0;u<4;++u)
        #pragma unroll
        for (int v=0;v<8;++v) acc[u][v]=0.f;
    float mu[4], rs[4];
    #pragma unroll
    for (int u=0;u<4;++u){ mu[u]=mu_s[ty*4+u]; rs[u]=rs_s[ty*4+u]; }
    const float* zwT = g_wT + 5*CH*CH;

    for (int h0=0;h0<CH;h0+=16){
        #pragma unroll
        for (int it=0; it<2; ++it){
            int f=tid+it*256;
            int hh=f>>5, o4=f&31;
            *(float4*)(zw_s + hh*132 + o4*4) = *(const float4*)(zwT + (h0+hh)*CH + o4*4);
        }
        __syncthreads();
        #pragma unroll
        for (int hh=0; hh<16; ++hh){
            int h=h0+hh;
            float lw=low_s[h], lb=lob_s[h];
            float xn[4];
            #pragma unroll
            for (int u=0;u<4;++u) xn[u] = (xs[h*66 + ty*4+u]-mu[u])*rs[u]*lw + lb;
            float w[8];
            *(float4*)(w)   = *(float4*)(zw_s + hh*132 + tx*8);
            *(float4*)(w+4) = *(float4*)(zw_s + hh*132 + tx*8 + 4);
            #pragma unroll
            for (int u=0;u<4;++u)
                #pragma unroll
                for (int v=0;v<8;++v) acc[u][v] += xn[u]*w[v];
        }
        __syncthreads();
    }
    #pragma unroll
    for (int u=0;u<4;++u){
        int grow=row0+ty*4+u;
        const float4* g4 = (const float4*)(g_gate + (size_t)grow*CH + tx*8);
        const float4* b4 = (const float4*)(zb + tx*8);
        float4* o4p = (float4*)(out + (size_t)grow*CH + tx*8);
        #pragma unroll
        for (int w2=0;w2<2;++w2){
            float4 g=g4[w2], b=b4[w2];
            o4p[w2] = make_float4(g.x*(acc[u][w2*4+0]+b.x),
                                  g.y*(acc[u][w2*4+1]+b.y),
                                  g.z*(acc[u][w2*4+2]+b.z),
                                  g.w*(acc[u][w2*4+3]+b.w));
        }
    }
}

extern "C" void kernel_launch(void* const* d_in, const int* in_sizes, int n_in,
                              void* d_out, int out_size) {
    const float* z      = (const float*)d_in[0];
    const float* mask   = (const float*)d_in[1];
    const float* ln_in_w= (const float*)d_in[2];
    const float* ln_in_b= (const float*)d_in[3];
    const float* a_g_w  = (const float*)d_in[4];
    const float* a_g_b  = (const float*)d_in[5];
    const float* a_p_w  = (const float*)d_in[6];
    const float* a_p_b  = (const float*)d_in[7];
    const float* b_g_w  = (const float*)d_in[8];
    const float* b_g_b  = (const float*)d_in[9];
    const float* b_p_w  = (const float*)d_in[10];
    const float* b_p_b  = (const float*)d_in[11];
    const float* g_w    = (const float*)d_in[12];
    const float* g_b    = (const float*)d_in[13];
    const float* ln_out_w=(const float*)d_in[14];
    const float* ln_out_b=(const float*)d_in[15];
    const float* z_w    = (const float*)d_in[16];
    const float* z_b    = (const float*)d_in[17];
    float* out = (float*)d_out;

    transpose_all<<<dim3(4,4,6), dim3(32,8)>>>(a_g_w, a_p_w, b_g_w, b_p_w, g_w, z_w);
    proj_kernel<<<NN/32,256>>>(z, mask, ln_in_w, ln_in_b,
                               a_g_b, a_p_b, b_g_b, b_p_b, g_b);
    tri_mma_kernel<<<dim3(3,3,CH), 256>>>();
    out_kernel<<<NN/64,256>>>(ln_out_w, ln_out_b, z_b, out);
}

// round 6
// speedup vs baseline: 2.5501x; 2.5501x over previous
#include <cuda_runtime.h>
#include <cuda_bf16.h>
#include <cstdint>

#define NRES 384
#define CH 128
#define NN (NRES*NRES)
#define EPSF 1e-5f
#define KSPLIT (3*NRES)   // 1152 (triangle K')
#define KP 384            // proj K' = 3*128
#define BKP 32
#define NCHP (KP/BKP)     // 12

// ---- scratch (device globals; no allocation) ----
__device__ __nv_bfloat16 g_as[(size_t)CH*NRES*KSPLIT]; // A' per h: [o][i][slot*384+k]  = [hi|lo|hi]
__device__ __nv_bfloat16 g_bs[(size_t)CH*NRES*KSPLIT]; // B' per h: [o][j][slot*384+k]  = [hi|hi|lo]
__device__ __nv_bfloat16 g_zs[(size_t)NN*KP];          // zn split rows: [zh(128)|zl|zh]
__device__ __nv_bfloat16 g_ws[(size_t)5*CH*KP];        // W' rows: [Wh|Wh|Wl]
__device__ float g_gate[(size_t)NN*CH];
__device__ float g_xt[(size_t)CH*NN];
__device__ float g_wT[6*CH*CH];

__device__ __forceinline__ float sigf(float x){ return 1.f/(1.f+__expf(-x)); }

__device__ __forceinline__ uint32_t s2u(const void* p){
    uint32_t a;
    asm("{ .reg .u64 t; cvta.to.shared.u64 t, %1; cvt.u32.u64 %0, t; }" : "=r"(a) : "l"(p));
    return a;
}
__device__ __forceinline__ void ldsm4(uint32_t &r0,uint32_t &r1,uint32_t &r2,uint32_t &r3,uint32_t a){
    asm volatile("ldmatrix.sync.aligned.m8n8.x4.shared.b16 {%0,%1,%2,%3}, [%4];"
        : "=r"(r0),"=r"(r1),"=r"(r2),"=r"(r3) : "r"(a));
}
__device__ __forceinline__ void mma16816(float* d, const uint32_t* a, const uint32_t* b){
    asm volatile("mma.sync.aligned.m16n8k16.row.col.f32.bf16.bf16.f32 "
        "{%0,%1,%2,%3}, {%4,%5,%6,%7}, {%8,%9}, {%0,%1,%2,%3};"
        : "+f"(d[0]),"+f"(d[1]),"+f"(d[2]),"+f"(d[3])
        : "r"(a[0]),"r"(a[1]),"r"(a[2]),"r"(a[3]), "r"(b[0]),"r"(b[1]));
}
__device__ __forceinline__ void cpa(uint32_t d, const void* s){
    asm volatile("cp.async.ca.shared.global [%0], [%1], 16;" :: "r"(d), "l"(s) : "memory");
}
__device__ __forceinline__ void cp_commit(){ asm volatile("cp.async.commit_group;" ::: "memory"); }
template<int N> __device__ __forceinline__ void cp_wait(){ asm volatile("cp.async.wait_group %0;" :: "n"(N) : "memory"); }

// ---- 128x128 transpose (z_w only, into g_wT[5]) ----
__global__ void transpose128(const float* __restrict__ src, int idx){
    __shared__ float t[32][33];
    float* dst = g_wT + idx*CH*CH;
    int x0=blockIdx.x*32, y0=blockIdx.y*32;
    int tx=threadIdx.x, ty=threadIdx.y;
    #pragma unroll
    for (int j=0;j<32;j+=8) t[ty+j][tx] = src[(y0+ty+j)*CH + x0+tx];
    __syncthreads();
    #pragma unroll
    for (int j=0;j<32;j+=8) dst[(x0+ty+j)*CH + y0+tx] = t[tx][ty+j];
}

// ---- split 5 projection weights into bf16 [Wh|Wh|Wl], K-major rows ----
__global__ void wsplit_kernel(const float* w0, const float* w1, const float* w2,
                              const float* w3, const float* w4){
    const float* srcs[5] = {w0,w1,w2,w3,w4};
    const float* W = srcs[blockIdx.x];
    __nv_bfloat16* dst = g_ws + (size_t)blockIdx.x*CH*KP;
    for (int it=0; it<64; ++it){
        int idx = threadIdx.x + it*256;
        int o = idx>>7, k = idx&127;
        float v = W[idx];
        __nv_bfloat16 hi = __float2bfloat16(v);
        __nv_bfloat16 lo = __float2bfloat16(v - __bfloat162float(hi));
        dst[(size_t)o*KP + k]       = hi;
        dst[(size_t)o*KP + 128 + k] = hi;
        dst[(size_t)o*KP + 256 + k] = lo;
    }
}

// ---- LN(z) -> split bf16 rows [zh|zl|zh] ----
__global__ __launch_bounds__(256)
void ln_split_kernel(const float* __restrict__ z,
                     const float* __restrict__ lnw, const float* __restrict__ lnb){
    int tid=threadIdx.x, wid=tid>>5, lane=tid&31;
    size_t row = (size_t)blockIdx.x*8 + wid;
    float4 v = *(const float4*)(z + row*CH + lane*4);
    float s = v.x+v.y+v.z+v.w;
    float q = v.x*v.x+v.y*v.y+v.z*v.z+v.w*v.w;
    #pragma unroll
    for (int o=16;o>0;o>>=1){ s+=__shfl_xor_sync(0xffffffffu,s,o); q+=__shfl_xor_sync(0xffffffffu,q,o); }
    float mu=s*(1.f/128.f), var=q*(1.f/128.f)-mu*mu;
    float rs=rsqrtf(fmaxf(var,0.f)+EPSF);
    float4 w4 = *(const float4*)(lnw + lane*4);
    float4 b4 = *(const float4*)(lnb + lane*4);
    float n[4] = {(v.x-mu)*rs*w4.x+b4.x, (v.y-mu)*rs*w4.y+b4.y,
                  (v.z-mu)*rs*w4.z+b4.z, (v.w-mu)*rs*w4.w+b4.w};
    __nv_bfloat16 hi[4], lo[4];
    #pragma unroll
    for (int j=0;j<4;++j){
        hi[j] = __float2bfloat16(n[j]);
        lo[j] = __float2bfloat16(n[j]-__bfloat162float(hi[j]));
    }
    __nv_bfloat16* d = g_zs + row*KP + lane*4;
    *(__nv_bfloat162*)(d)       = __nv_bfloat162{hi[0],hi[1]};
    *(__nv_bfloat162*)(d+2)     = __nv_bfloat162{hi[2],hi[3]};
    *(__nv_bfloat162*)(d+128)   = __nv_bfloat162{lo[0],lo[1]};
    *(__nv_bfloat162*)(d+130)   = __nv_bfloat162{lo[2],lo[3]};
    *(__nv_bfloat162*)(d+256)   = __nv_bfloat162{hi[0],hi[1]};
    *(__nv_bfloat162*)(d+258)   = __nv_bfloat162{hi[2],hi[3]};
}

// ---- proj on tensor cores: per (i-tile, phase) ----
// phase 0: (a_g, a_p) -> g_as   phase 1: (b_g, b_p) -> g_bs   phase 2: g_w -> g_gate
#define LDP 40
#define PBUF 10240u

__device__ __forceinline__ void proj_issue(int tid, int c, int buf, bool hasP,
    uint32_t sA, uint32_t sG, uint32_t sP,
    const __nv_bfloat16* Az, const __nv_bfloat16* WG, const __nv_bfloat16* WP){
    #pragma unroll
    for (int it=0; it<2; ++it){
        int idx = tid + it*256;
        int row = idx>>2, seg = idx&3;
        uint32_t off = (uint32_t)buf*PBUF + (uint32_t)(row*80 + seg*16);
        size_t gof = (size_t)row*KP + c*BKP + seg*8;
        cpa(sA + off, Az + gof);
        cpa(sG + off, WG + gof);
        if (hasP) cpa(sP + off, WP + gof);
    }
    cp_commit();
}

__global__ __launch_bounds__(256,1)
void projmma_kernel(const float* __restrict__ mask_,
                    const float* __restrict__ agb, const float* __restrict__ apb,
                    const float* __restrict__ bgb, const float* __restrict__ bpb,
                    const float* __restrict__ gb_)
{
    extern __shared__ char sm[];
    uint32_t sA = s2u(sm);
    uint32_t sG = sA + 2*PBUF;
    uint32_t sP = sA + 4*PBUF;
    float* ot = (float*)sm;

    int tid=threadIdx.x, wid=tid>>5, lane=tid&31;
    int wm=wid&1, wn=wid>>1;
    int t = blockIdx.x, ph = blockIdx.y;
    bool hasP = ph<2;
    const __nv_bfloat16* WG = g_ws + (size_t)(hasP ? 2*ph : 4)*CH*KP;
    const __nv_bfloat16* WP = g_ws + (size_t)(hasP ? 2*ph+1 : 4)*CH*KP;
    const float* GBp = (ph==0)?agb:((ph==1)?bgb:gb_);
    const float* PBp = (ph==0)?apb:bpb;
    const __nv_bfloat16* Az = g_zs + (size_t)t*128*KP;

    float accG[4][4][4], accP[4][4][4];
    #pragma unroll
    for (int mf=0;mf<4;++mf)
        #pragma unroll
        for (int nf=0;nf<4;++nf)
            #pragma unroll
            for (int r=0;r<4;++r){ accG[mf][nf][r]=0.f; accP[mf][nf][r]=0.f; }

    proj_issue(tid, 0, 0, hasP, sA, sG, sP, Az, WG, WP);

    for (int c=0; c<NCHP; ++c){
        int buf = c & 1;
        if (c+1<NCHP){ proj_issue(tid, c+1, buf^1, hasP, sA, sG, sP, Az, WG, WP); cp_wait<1>(); }
        else cp_wait<0>();
        __syncthreads();
        uint32_t bofs = (uint32_t)buf*PBUF;
        #pragma unroll
        for (int ks=0; ks<2; ++ks){
            uint32_t a[4][4];
            #pragma unroll
            for (int mf=0; mf<4; ++mf){
                int row = wm*64 + mf*16 + (lane&15);
                int kc  = ks*16 + (lane>>4)*8;
                ldsm4(a[mf][0],a[mf][1],a[mf][2],a[mf][3], sA + bofs + (uint32_t)(row*LDP + kc)*2);
            }
            uint32_t bg[4][2], bp[4][2];
            #pragma unroll
            for (int nf2=0; nf2<2; ++nf2){
                int nrow = wn*32 + nf2*16 + (lane&7) + ((lane>>4)<<3);
                int kc   = ks*16 + ((lane>>3)&1)*8;
                uint32_t r0,r1,r2,r3;
                ldsm4(r0,r1,r2,r3, sG + bofs + (uint32_t)(nrow*LDP + kc)*2);
                bg[nf2*2+0][0]=r0; bg[nf2*2+0][1]=r1; bg[nf2*2+1][0]=r2; bg[nf2*2+1][1]=r3;
                if (hasP){
                    ldsm4(r0,r1,r2,r3, sP + bofs + (uint32_t)(nrow*LDP + kc)*2);
                    bp[nf2*2+0][0]=r0; bp[nf2*2+0][1]=r1; bp[nf2*2+1][0]=r2; bp[nf2*2+1][1]=r3;
                }
            }
            #pragma unroll
            for (int mf=0; mf<4; ++mf)
                #pragma unroll
                for (int nf=0; nf<4; ++nf){
                    mma16816(accG[mf][nf], a[mf], bg[nf]);
                    if (hasP) mma16816(accP[mf][nf], a[mf], bp[nf]);
                }
        }
        __syncthreads();
    }

    if (hasP){
        __nv_bfloat16* dst = ph ? g_bs : g_as;
        int i_idx = t/3, k0 = (t%3)*128;
        #pragma unroll
        for (int half=0; half<2; ++half){
            __syncthreads();
            if ((wn>>1)==half){
                #pragma unroll
                for (int mf=0; mf<4; ++mf)
                    #pragma unroll
                    for (int nf=0; nf<4; ++nf){
                        int col = wn*32 + nf*8 + (lane&3)*2;
                        int oc  = col & 63;
                        int row = wm*64 + mf*16 + (lane>>2);
                        float mk0 = __ldg(mask_ + t*128 + row);
                        float mk1 = __ldg(mask_ + t*128 + row + 8);
                        float g0=__ldg(GBp+col), g1=__ldg(GBp+col+1);
                        float p0=__ldg(PBp+col), p1=__ldg(PBp+col+1);
                        ot[oc*132+row]        = mk0*sigf(accG[mf][nf][0]+g0)*(accP[mf][nf][0]+p0);
                        ot[(oc+1)*132+row]    = mk0*sigf(accG[mf][nf][1]+g1)*(accP[mf][nf][1]+p1);
                        ot[oc*132+row+8]      = mk1*sigf(accG[mf][nf][2]+g0)*(accP[mf][nf][2]+p0);
                        ot[(oc+1)*132+row+8]  = mk1*sigf(accG[mf][nf][3]+g1)*(accP[mf][nf][3]+p1);
                    }
            }
            __syncthreads();
            #pragma unroll
            for (int it2=0; it2<32; ++it2){
                int f = tid + it2*256;
                int oloc = f>>7, r = f&127;
                int o = half*64 + oloc;
                float v = ot[oloc*132 + r];
                __nv_bfloat16 hi = __float2bfloat16(v);
                __nv_bfloat16 lo = __float2bfloat16(v - __bfloat162float(hi));
                size_t base = (size_t)o*(NRES*KSPLIT) + (size_t)i_idx*KSPLIT + (k0 + r);
                if (ph==0){ dst[base]=hi; dst[base+NRES]=lo; dst[base+2*NRES]=hi; }
                else      { dst[base]=hi; dst[base+NRES]=hi; dst[base+2*NRES]=lo; }
            }
        }
    } else {
        #pragma unroll
        for (int mf=0; mf<4; ++mf)
            #pragma unroll
            for (int nf=0; nf<4; ++nf){
                int col = wn*32 + nf*8 + (lane&3)*2;
                int row = wm*64 + mf*16 + (lane>>2);
                size_t R0 = (size_t)t*128 + row;
                float g0=__ldg(GBp+col), g1=__ldg(GBp+col+1);
                *(float2*)(g_gate + R0*CH + col) =
                    make_float2(sigf(accG[mf][nf][0]+g0), sigf(accG[mf][nf][1]+g1));
                *(float2*)(g_gate + (R0+8)*CH + col) =
                    make_float2(sigf(accG[mf][nf][2]+g0), sigf(accG[mf][nf][3]+g1));
            }
    }
}

// ---- triangle GEMM on mma.sync bf16 (unchanged from R5) ----
#define BK 32
#define LDA 40
#define NCH (KSPLIT/BK) // 36

__global__ __launch_bounds__(256)
void tri_mma_kernel(){
    __shared__ __nv_bfloat16 As[2][128*LDA];
    __shared__ __nv_bfloat16 Bs[2][128*LDA];

    int tid = threadIdx.x;
    int wid = tid>>5, lane = tid&31;
    int wm = wid & 1, wn = wid >> 1;
    int h = blockIdx.z, i0 = blockIdx.y*128, j0 = blockIdx.x*128;

    const __nv_bfloat16* Ag = g_as + ((size_t)h*NRES + i0)*KSPLIT;
    const __nv_bfloat16* Bg = g_bs + ((size_t)h*NRES + j0)*KSPLIT;

    float acc[4][4][4];
    #pragma unroll
    for (int mf=0;mf<4;++mf)
        #pragma unroll
        for (int nf=0;nf<4;++nf)
            #pragma unroll
            for (int r=0;r<4;++r) acc[mf][nf][r]=0.f;

    int lrow = tid>>2, lsub = tid&3;
    #pragma unroll
    for (int half=0; half<2; ++half){
        int row = lrow + half*64;
        *(uint4*)(&As[0][row*LDA + lsub*8]) = *(const uint4*)(Ag + (size_t)row*KSPLIT + lsub*8);
        *(uint4*)(&Bs[0][row*LDA + lsub*8]) = *(const uint4*)(Bg + (size_t)row*KSPLIT + lsub*8);
    }
    __syncthreads();

    for (int c=0; c<NCH; ++c){
        int buf = c & 1;
        uint4 pa[2], pb[2];
        if (c+1 < NCH){
            #pragma unroll
            for (int half=0; half<2; ++half){
                int row = lrow + half*64;
                pa[half] = *(const uint4*)(Ag + (size_t)row*KSPLIT + (c+1)*BK + lsub*8);
                pb[half] = *(const uint4*)(Bg + (size_t)row*KSPLIT + (c+1)*BK + lsub*8);
            }
        }
        uint32_t as_base = s2u(&As[buf][0]);
        uint32_t bs_base = s2u(&Bs[buf][0]);
        #pragma unroll
        for (int ks=0; ks<2; ++ks){
            uint32_t a[4][4];
            #pragma unroll
            for (int mf=0; mf<4; ++mf){
                int row = wm*64 + mf*16 + (lane&15);
                int kc  = ks*16 + (lane>>4)*8;
                ldsm4(a[mf][0],a[mf][1],a[mf][2],a[mf][3], as_base + (row*LDA + kc)*2);
            }
            uint32_t b[4][2];
            #pragma unroll
            for (int nf2=0; nf2<2; ++nf2){
                int nrow = wn*32 + nf2*16 + (lane&7) + ((lane>>4)<<3);
                int kc   = ks*16 + ((lane>>3)&1)*8;
                uint32_t r0,r1,r2,r3;
                ldsm4(r0,r1,r2,r3, bs_base + (nrow*LDA + kc)*2);
                b[nf2*2+0][0]=r0; b[nf2*2+0][1]=r1;
                b[nf2*2+1][0]=r2; b[nf2*2+1][1]=r3;
            }
            #pragma unroll
            for (int mf=0; mf<4; ++mf)
                #pragma unroll
                for (int nf=0; nf<4; ++nf)
                    mma16816(acc[mf][nf], a[mf], b[nf]);
        }
        if (c+1 < NCH){
            int nbuf = buf^1;
            #pragma unroll
            for (int half=0; half<2; ++half){
                int row = lrow + half*64;
                *(uint4*)(&As[nbuf][row*LDA + lsub*8]) = pa[half];
                *(uint4*)(&Bs[nbuf][row*LDA + lsub*8]) = pb[half];
            }
        }
        __syncthreads();
    }

    float* X = g_xt + (size_t)h*NN;
    #pragma unroll
    for (int mf=0; mf<4; ++mf){
        #pragma unroll
        for (int nf=0; nf<4; ++nf){
            int row = i0 + wm*64 + mf*16 + (lane>>2);
            int col = j0 + wn*32 + nf*8 + (lane&3)*2;
            *(float2*)(X + (size_t)row*NRES + col)     = make_float2(acc[mf][nf][0], acc[mf][nf][1]);
            *(float2*)(X + (size_t)(row+8)*NRES + col) = make_float2(acc[mf][nf][2], acc[mf][nf][3]);
        }
    }
}

// ---- LN over h + output GEMM + gate; 64 rows/block (unchanged) ----
__global__ __launch_bounds__(256)
void out_kernel(const float* __restrict__ low, const float* __restrict__ lob,
                const float* __restrict__ zb, float* __restrict__ out)
{
    __shared__ float xs[128*66];
    __shared__ float zw_s[16*132];
    __shared__ float mu_s[64], rs_s[64];
    __shared__ float low_s[128], lob_s[128];
    int tid=threadIdx.x;
    int row0 = blockIdx.x*64;
    if (tid<128){ low_s[tid]=low[tid]; lob_s[tid]=lob[tid]; }
    #pragma unroll
    for (int it=0; it<32; ++it){
        int f = tid + it*256;
        int r = f&63, h = f>>6;
        xs[h*66 + r] = g_xt[(size_t)h*NN + row0 + r];
    }
    __syncthreads();
    int lane=tid&31, wid=tid>>5;
    #pragma unroll
    for (int rr=0;rr<8;++rr){
        int r = wid*8+rr;
        float s=0.f,q=0.f;
        #pragma unroll
        for (int m=0;m<4;++m){ float x=xs[(lane+32*m)*66 + r]; s+=x; q+=x*x; }
        #pragma unroll
        for (int o=16;o>0;o>>=1){ s+=__shfl_xor_sync(0xffffffffu,s,o); q+=__shfl_xor_sync(0xffffffffu,q,o); }
        if (lane==0){
            float mu=s*(1.f/128.f), var=q*(1.f/128.f)-mu*mu;
            mu_s[r]=mu; rs_s[r]=rsqrtf(fmaxf(var,0.f)+EPSF);
        }
    }
    __syncthreads();
    int tx=tid&15, ty=tid>>4;
    float acc[4][8];
    #pragma unroll
    for (int u=0;u<4;++u)
        #pragma unroll
        for (int v=0;v<8;++v) acc[u][v]=0.f;
    float mu[4], rs[4];
    #pragma unroll
    for (int u=0;u<4;++u){ mu[u]=mu_s[ty*4+u]; rs[u]=rs_s[ty*4+u]; }
    const float* zwT = g_wT + 5*CH*CH;

    for (int h0=0;h0<CH;h0+=16){
        #pragma unroll
        for (int it=0; it<2; ++it){
            int f=tid+it*256;
            int hh=f>>5, o4=f&31;
            *(float4*)(zw_s + hh*132 + o4*4) = *(const float4*)(zwT + (h0+hh)*CH + o4*4);
        }
        __syncthreads();
        #pragma unroll
        for (int hh=0; hh<16; ++hh){
            int h=h0+hh;
            float lw=low_s[h], lb=lob_s[h];
            float xn[4];
            #pragma unroll
            for (int u=0;u<4;++u) xn[u] = (xs[h*66 + ty*4+u]-mu[u])*rs[u]*lw + lb;
            float w[8];
            *(float4*)(w)   = *(float4*)(zw_s + hh*132 + tx*8);
            *(float4*)(w+4) = *(float4*)(zw_s + hh*132 + tx*8 + 4);
            #pragma unroll
            for (int u=0;u<4;++u)
                #pragma unroll
                for (int v=0;v<8;++v) acc[u][v] += xn[u]*w[v];
        }
        __syncthreads();
    }
    #pragma unroll
    for (int u=0;u<4;++u){
        int grow=row0+ty*4+u;
        const float4* g4 = (const float4*)(g_gate + (size_t)grow*CH + tx*8);
        const float4* b4 = (const float4*)(zb + tx*8);
        float4* o4p = (float4*)(out + (size_t)grow*CH + tx*8);
        #pragma unroll
        for (int w2=0;w2<2;++w2){
            float4 g=g4[w2], b=b4[w2];
            o4p[w2] = make_float4(g.x*(acc[u][w2*4+0]+b.x),
                                  g.y*(acc[u][w2*4+1]+b.y),
                                  g.z*(acc[u][w2*4+2]+b.z),
                                  g.w*(acc[u][w2*4+3]+b.w));
        }
    }
}

extern "C" void kernel_launch(void* const* d_in, const int* in_sizes, int n_in,
                              void* d_out, int out_size) {
    const float* z      = (const float*)d_in[0];
    const float* mask   = (const float*)d_in[1];
    const float* ln_in_w= (const float*)d_in[2];
    const float* ln_in_b= (const float*)d_in[3];
    const float* a_g_w  = (const float*)d_in[4];
    const float* a_g_b  = (const float*)d_in[5];
    const float* a_p_w  = (const float*)d_in[6];
    const float* a_p_b  = (const float*)d_in[7];
    const float* b_g_w  = (const float*)d_in[8];
    const float* b_g_b  = (const float*)d_in[9];
    const float* b_p_w  = (const float*)d_in[10];
    const float* b_p_b  = (const float*)d_in[11];
    const float* g_w    = (const float*)d_in[12];
    const float* g_b    = (const float*)d_in[13];
    const float* ln_out_w=(const float*)d_in[14];
    const float* ln_out_b=(const float*)d_in[15];
    const float* z_w    = (const float*)d_in[16];
    const float* z_b    = (const float*)d_in[17];
    float* out = (float*)d_out;

    cudaFuncSetAttribute(projmma_kernel, cudaFuncAttributeMaxDynamicSharedMemorySize, 61440);

    transpose128<<<dim3(4,4), dim3(32,8)>>>(z_w, 5);
    wsplit_kernel<<<5,256>>>(a_g_w, a_p_w, b_g_w, b_p_w, g_w);
    ln_split_kernel<<<NN/8,256>>>(z, ln_in_w, ln_in_b);
    projmma_kernel<<<dim3(1152,3),256,61440>>>(mask, a_g_b, a_p_b, b_g_b, b_p_b, g_b);
    tri_mma_kernel<<<dim3(3,3,CH),256>>>();
    out_kernel<<<NN/64,256>>>(ln_out_w, ln_out_b, z_b, out);
}

// round 7
// speedup vs baseline: 3.0916x; 1.2123x over previous
#include <cuda_runtime.h>
#include <cuda_bf16.h>
#include <cstdint>

#define NRES 384
#define CH 128
#define NN (NRES*NRES)
#define EPSF 1e-5f
#define KSPLIT (3*NRES)   // 1152 (triangle K')
#define KP 384            // proj K' = 3*128
#define BKP 32
#define NCHP (KP/BKP)     // 12

// ---- scratch (device globals; no allocation) ----
__device__ __nv_bfloat16 g_as[(size_t)CH*NRES*KSPLIT];
__device__ __nv_bfloat16 g_bs[(size_t)CH*NRES*KSPLIT];
__device__ __nv_bfloat16 g_zs[(size_t)NN*KP];
__device__ __nv_bfloat16 g_ws[(size_t)5*CH*KP];
__device__ float g_gate[(size_t)NN*CH];
__device__ float g_xt[(size_t)CH*NN];
__device__ float g_wT[6*CH*CH];

__device__ __forceinline__ float sigf(float x){ return 1.f/(1.f+__expf(-x)); }

__device__ __forceinline__ uint32_t s2u(const void* p){
    uint32_t a;
    asm("{ .reg .u64 t; cvta.to.shared.u64 t, %1; cvt.u32.u64 %0, t; }" : "=r"(a) : "l"(p));
    return a;
}
__device__ __forceinline__ void ldsm4(uint32_t &r0,uint32_t &r1,uint32_t &r2,uint32_t &r3,uint32_t a){
    asm volatile("ldmatrix.sync.aligned.m8n8.x4.shared.b16 {%0,%1,%2,%3}, [%4];"
        : "=r"(r0),"=r"(r1),"=r"(r2),"=r"(r3) : "r"(a));
}
__device__ __forceinline__ void mma16816(float* d, const uint32_t* a, const uint32_t* b){
    asm volatile("mma.sync.aligned.m16n8k16.row.col.f32.bf16.bf16.f32 "
        "{%0,%1,%2,%3}, {%4,%5,%6,%7}, {%8,%9}, {%0,%1,%2,%3};"
        : "+f"(d[0]),"+f"(d[1]),"+f"(d[2]),"+f"(d[3])
        : "r"(a[0]),"r"(a[1]),"r"(a[2]),"r"(a[3]), "r"(b[0]),"r"(b[1]));
}
__device__ __forceinline__ void cpa(uint32_t d, const void* s){
    asm volatile("cp.async.ca.shared.global [%0], [%1], 16;" :: "r"(d), "l"(s) : "memory");
}
__device__ __forceinline__ void cp_commit(){ asm volatile("cp.async.commit_group;" ::: "memory"); }
template<int N> __device__ __forceinline__ void cp_wait(){ asm volatile("cp.async.wait_group %0;" :: "n"(N) : "memory"); }

// ---- 128x128 transpose (z_w only) ----
__global__ void transpose128(const float* __restrict__ src, int idx){
    __shared__ float t[32][33];
    float* dst = g_wT + idx*CH*CH;
    int x0=blockIdx.x*32, y0=blockIdx.y*32;
    int tx=threadIdx.x, ty=threadIdx.y;
    #pragma unroll
    for (int j=0;j<32;j+=8) t[ty+j][tx] = src[(y0+ty+j)*CH + x0+tx];
    __syncthreads();
    #pragma unroll
    for (int j=0;j<32;j+=8) dst[(x0+ty+j)*CH + y0+tx] = t[tx][ty+j];
}

// ---- split 5 projection weights into bf16 [Wh|Wh|Wl] ----
__global__ void wsplit_kernel(const float* w0, const float* w1, const float* w2,
                              const float* w3, const float* w4){
    const float* srcs[5] = {w0,w1,w2,w3,w4};
    const float* W = srcs[blockIdx.x];
    __nv_bfloat16* dst = g_ws + (size_t)blockIdx.x*CH*KP;
    for (int it=0; it<64; ++it){
        int idx = threadIdx.x + it*256;
        int o = idx>>7, k = idx&127;
        float v = W[idx];
        __nv_bfloat16 hi = __float2bfloat16(v);
        __nv_bfloat16 lo = __float2bfloat16(v - __bfloat162float(hi));
        dst[(size_t)o*KP + k]       = hi;
        dst[(size_t)o*KP + 128 + k] = hi;
        dst[(size_t)o*KP + 256 + k] = lo;
    }
}

// ---- LN(z) -> split bf16 rows [zh|zl|zh] ----
__global__ __launch_bounds__(256)
void ln_split_kernel(const float* __restrict__ z,
                     const float* __restrict__ lnw, const float* __restrict__ lnb){
    int tid=threadIdx.x, wid=tid>>5, lane=tid&31;
    size_t row = (size_t)blockIdx.x*8 + wid;
    float4 v = *(const float4*)(z + row*CH + lane*4);
    float s = v.x+v.y+v.z+v.w;
    float q = v.x*v.x+v.y*v.y+v.z*v.z+v.w*v.w;
    #pragma unroll
    for (int o=16;o>0;o>>=1){ s+=__shfl_xor_sync(0xffffffffu,s,o); q+=__shfl_xor_sync(0xffffffffu,q,o); }
    float mu=s*(1.f/128.f), var=q*(1.f/128.f)-mu*mu;
    float rs=rsqrtf(fmaxf(var,0.f)+EPSF);
    float4 w4 = *(const float4*)(lnw + lane*4);
    float4 b4 = *(const float4*)(lnb + lane*4);
    float n[4] = {(v.x-mu)*rs*w4.x+b4.x, (v.y-mu)*rs*w4.y+b4.y,
                  (v.z-mu)*rs*w4.z+b4.z, (v.w-mu)*rs*w4.w+b4.w};
    __nv_bfloat16 hi[4], lo[4];
    #pragma unroll
    for (int j=0;j<4;++j){
        hi[j] = __float2bfloat16(n[j]);
        lo[j] = __float2bfloat16(n[j]-__bfloat162float(hi[j]));
    }
    __nv_bfloat16* d = g_zs + row*KP + lane*4;
    *(__nv_bfloat162*)(d)       = __nv_bfloat162{hi[0],hi[1]};
    *(__nv_bfloat162*)(d+2)     = __nv_bfloat162{hi[2],hi[3]};
    *(__nv_bfloat162*)(d+128)   = __nv_bfloat162{lo[0],lo[1]};
    *(__nv_bfloat162*)(d+130)   = __nv_bfloat162{lo[2],lo[3]};
    *(__nv_bfloat162*)(d+256)   = __nv_bfloat162{hi[0],hi[1]};
    *(__nv_bfloat162*)(d+258)   = __nv_bfloat162{hi[2],hi[3]};
}

// ---- proj on tensor cores: 64-row tiles, grid (2304, 3) ----
// phase 0: (a_g,a_p)->g_as  phase 1: (b_g,b_p)->g_bs  phase 2: g_w->g_gate
#define LDP 40
#define ABUF 5120u    // 64*80
#define WBUF 10240u   // 128*80
#define STEP 25600u   // ABUF + 2*WBUF

__device__ __forceinline__ void proj_issue(int tid, int c, int buf, bool hasP,
    uint32_t sA, uint32_t sG, uint32_t sP,
    const __nv_bfloat16* Az, const __nv_bfloat16* WG, const __nv_bfloat16* WP){
    uint32_t bofs = (uint32_t)buf*STEP;
    {   // A: 64 rows x 4 segs = 256 ops
        int row = tid>>2, seg = tid&3;
        cpa(sA + bofs + (uint32_t)(row*80 + seg*16), Az + (size_t)row*KP + c*BKP + seg*8);
    }
    #pragma unroll
    for (int it=0; it<2; ++it){   // G (and P): 128 rows x 4 segs = 512 ops each
        int idx = tid + it*256;
        int row = idx>>2, seg = idx&3;
        uint32_t off = bofs + (uint32_t)(row*80 + seg*16);
        size_t gof = (size_t)row*KP + c*BKP + seg*8;
        cpa(sG + off, WG + gof);
        if (hasP) cpa(sP + off, WP + gof);
    }
    cp_commit();
}

__global__ __launch_bounds__(256,2)
void projmma_kernel(const float* __restrict__ mask_,
                    const float* __restrict__ agb, const float* __restrict__ apb,
                    const float* __restrict__ bgb, const float* __restrict__ bpb,
                    const float* __restrict__ gb_)
{
    extern __shared__ char sm[];
    uint32_t sA = s2u(sm);
    uint32_t sG = sA + ABUF;
    uint32_t sP = sG + WBUF;
    float* ot = (float*)sm;

    int tid=threadIdx.x, wid=tid>>5, lane=tid&31;
    int wm=wid&1, wn=wid>>1;          // 2 x 4 warps; warp tile 32x32
    int t2 = blockIdx.x, ph = blockIdx.y;
    bool hasP = ph<2;
    const __nv_bfloat16* WG = g_ws + (size_t)(hasP ? 2*ph : 4)*CH*KP;
    const __nv_bfloat16* WP = g_ws + (size_t)(hasP ? 2*ph+1 : 4)*CH*KP;
    const float* GBp = (ph==0)?agb:((ph==1)?bgb:gb_);
    const float* PBp = (ph==0)?apb:bpb;
    const __nv_bfloat16* Az = g_zs + (size_t)t2*64*KP;

    float accG[2][4][4], accP[2][4][4];
    #pragma unroll
    for (int mf=0;mf<2;++mf)
        #pragma unroll
        for (int nf=0;nf<4;++nf)
            #pragma unroll
            for (int r=0;r<4;++r){ accG[mf][nf][r]=0.f; accP[mf][nf][r]=0.f; }

    proj_issue(tid, 0, 0, hasP, sA, sG, sP, Az, WG, WP);

    for (int c=0; c<NCHP; ++c){
        int buf = c & 1;
        if (c+1<NCHP){ proj_issue(tid, c+1, buf^1, hasP, sA, sG, sP, Az, WG, WP); cp_wait<1>(); }
        else cp_wait<0>();
        __syncthreads();
        uint32_t bofs = (uint32_t)buf*STEP;
        #pragma unroll
        for (int ks=0; ks<2; ++ks){
            uint32_t a[2][4];
            #pragma unroll
            for (int mf=0; mf<2; ++mf){
                int row = wm*32 + mf*16 + (lane&15);
                int kc  = ks*16 + (lane>>4)*8;
                ldsm4(a[mf][0],a[mf][1],a[mf][2],a[mf][3], sA + bofs + (uint32_t)(row*LDP + kc)*2);
            }
            uint32_t bg[4][2], bp[4][2];
            #pragma unroll
            for (int nf2=0; nf2<2; ++nf2){
                int nrow = wn*32 + nf2*16 + (lane&7) + ((lane>>4)<<3);
                int kc   = ks*16 + ((lane>>3)&1)*8;
                uint32_t r0,r1,r2,r3;
                ldsm4(r0,r1,r2,r3, sG + bofs + (uint32_t)(nrow*LDP + kc)*2);
                bg[nf2*2+0][0]=r0; bg[nf2*2+0][1]=r1; bg[nf2*2+1][0]=r2; bg[nf2*2+1][1]=r3;
                if (hasP){
                    ldsm4(r0,r1,r2,r3, sP + bofs + (uint32_t)(nrow*LDP + kc)*2);
                    bp[nf2*2+0][0]=r0; bp[nf2*2+0][1]=r1; bp[nf2*2+1][0]=r2; bp[nf2*2+1][1]=r3;
                }
            }
            #pragma unroll
            for (int mf=0; mf<2; ++mf)
                #pragma unroll
                for (int nf=0; nf<4; ++nf){
                    mma16816(accG[mf][nf], a[mf], bg[nf]);
                    if (hasP) mma16816(accP[mf][nf], a[mf], bp[nf]);
                }
        }
        __syncthreads();
    }

    if (hasP){
        __nv_bfloat16* dst = ph ? g_bs : g_as;
        int i_idx = t2/6, k0 = (t2%6)*64;
        // epilogue values -> ot[col][row] (transposed), 128 x 68 floats in smem
        #pragma unroll
        for (int mf=0; mf<2; ++mf)
            #pragma unroll
            for (int nf=0; nf<4; ++nf){
                int col = wn*32 + nf*8 + (lane&3)*2;
                int row = wm*32 + mf*16 + (lane>>2);
                float mk0 = __ldg(mask_ + t2*64 + row);
                float mk1 = __ldg(mask_ + t2*64 + row + 8);
                float g0=__ldg(GBp+col), g1=__ldg(GBp+col+1);
                float p0=__ldg(PBp+col), p1=__ldg(PBp+col+1);
                ot[col*68+row]       = mk0*sigf(accG[mf][nf][0]+g0)*(accP[mf][nf][0]+p0);
                ot[(col+1)*68+row]   = mk0*sigf(accG[mf][nf][1]+g1)*(accP[mf][nf][1]+p1);
                ot[col*68+row+8]     = mk1*sigf(accG[mf][nf][2]+g0)*(accP[mf][nf][2]+p0);
                ot[(col+1)*68+row+8] = mk1*sigf(accG[mf][nf][3]+g1)*(accP[mf][nf][3]+p1);
            }
        __syncthreads();
        #pragma unroll
        for (int it2=0; it2<32; ++it2){
            int f = tid + it2*256;
            int r = f&63, o = f>>6;
            float v = ot[o*68 + r];
            __nv_bfloat16 hi = __float2bfloat16(v);
            __nv_bfloat16 lo = __float2bfloat16(v - __bfloat162float(hi));
            size_t base = (size_t)o*(NRES*KSPLIT) + (size_t)i_idx*KSPLIT + (k0 + r);
            if (ph==0){ dst[base]=hi; dst[base+NRES]=lo; dst[base+2*NRES]=hi; }
            else      { dst[base]=hi; dst[base+NRES]=hi; dst[base+2*NRES]=lo; }
        }
    } else {
        #pragma unroll
        for (int mf=0; mf<2; ++mf)
            #pragma unroll
            for (int nf=0; nf<4; ++nf){
                int col = wn*32 + nf*8 + (lane&3)*2;
                int row = wm*32 + mf*16 + (lane>>2);
                size_t R0 = (size_t)t2*64 + row;
                float g0=__ldg(GBp+col), g1=__ldg(GBp+col+1);
                *(float2*)(g_gate + R0*CH + col) =
                    make_float2(sigf(accG[mf][nf][0]+g0), sigf(accG[mf][nf][1]+g1));
                *(float2*)(g_gate + (R0+8)*CH + col) =
                    make_float2(sigf(accG[mf][nf][2]+g0), sigf(accG[mf][nf][3]+g1));
            }
    }
}

// ---- triangle GEMM on mma.sync bf16, cp.async double-buffered ----
#define BK 32
#define LDA 40
#define NCH (KSPLIT/BK) // 36
#define TBUF 10240u     // 128*80

__device__ __forceinline__ void tri_issue(int tid, int c, int buf,
    const __nv_bfloat16* Ag, const __nv_bfloat16* Bg, uint32_t sAb, uint32_t sBb){
    int lrow = tid>>2, lsub = tid&3;
    #pragma unroll
    for (int half=0; half<2; ++half){
        int row = lrow + half*64;
        uint32_t off = (uint32_t)buf*TBUF + (uint32_t)(row*80 + lsub*16);
        cpa(sAb + off, Ag + (size_t)row*KSPLIT + c*BK + lsub*8);
        cpa(sBb + off, Bg + (size_t)row*KSPLIT + c*BK + lsub*8);
    }
    cp_commit();
}

__global__ __launch_bounds__(256,2)
void tri_mma_kernel(){
    __shared__ __nv_bfloat16 As[2][128*LDA];
    __shared__ __nv_bfloat16 Bs[2][128*LDA];

    int tid = threadIdx.x;
    int wid = tid>>5, lane = tid&31;
    int wm = wid & 1, wn = wid >> 1;
    int h = blockIdx.z, i0 = blockIdx.y*128, j0 = blockIdx.x*128;

    const __nv_bfloat16* Ag = g_as + ((size_t)h*NRES + i0)*KSPLIT;
    const __nv_bfloat16* Bg = g_bs + ((size_t)h*NRES + j0)*KSPLIT;
    uint32_t sAb = s2u(&As[0][0]);
    uint32_t sBb = s2u(&Bs[0][0]);

    float acc[4][4][4];
    #pragma unroll
    for (int mf=0;mf<4;++mf)
        #pragma unroll
        for (int nf=0;nf<4;++nf)
            #pragma unroll
            for (int r=0;r<4;++r) acc[mf][nf][r]=0.f;

    tri_issue(tid, 0, 0, Ag, Bg, sAb, sBb);

    for (int c=0; c<NCH; ++c){
        int buf = c & 1;
        if (c+1 < NCH){ tri_issue(tid, c+1, buf^1, Ag, Bg, sAb, sBb); cp_wait<1>(); }
        else cp_wait<0>();
        __syncthreads();
        uint32_t as_base = sAb + (uint32_t)buf*TBUF;
        uint32_t bs_base = sBb + (uint32_t)buf*TBUF;
        #pragma unroll
        for (int ks=0; ks<2; ++ks){
            uint32_t a[4][4];
            #pragma unroll
            for (int mf=0; mf<4; ++mf){
                int row = wm*64 + mf*16 + (lane&15);
                int kc  = ks*16 + (lane>>4)*8;
                ldsm4(a[mf][0],a[mf][1],a[mf][2],a[mf][3], as_base + (uint32_t)(row*LDA + kc)*2);
            }
            uint32_t b[4][2];
            #pragma unroll
            for (int nf2=0; nf2<2; ++nf2){
                int nrow = wn*32 + nf2*16 + (lane&7) + ((lane>>4)<<3);
                int kc   = ks*16 + ((lane>>3)&1)*8;
                uint32_t r0,r1,r2,r3;
                ldsm4(r0,r1,r2,r3, bs_base + (uint32_t)(nrow*LDA + kc)*2);
                b[nf2*2+0][0]=r0; b[nf2*2+0][1]=r1;
                b[nf2*2+1][0]=r2; b[nf2*2+1][1]=r3;
            }
            #pragma unroll
            for (int mf=0; mf<4; ++mf)
                #pragma unroll
                for (int nf=0; nf<4; ++nf)
                    mma16816(acc[mf][nf], a[mf], b[nf]);
        }
        __syncthreads();
    }

    float* X = g_xt + (size_t)h*NN;
    #pragma unroll
    for (int mf=0; mf<4; ++mf){
        #pragma unroll
        for (int nf=0; nf<4; ++nf){
            int row = i0 + wm*64 + mf*16 + (lane>>2);
            int col = j0 + wn*32 + nf*8 + (lane&3)*2;
            *(float2*)(X + (size_t)row*NRES + col)     = make_float2(acc[mf][nf][0], acc[mf][nf][1]);
            *(float2*)(X + (size_t)(row+8)*NRES + col) = make_float2(acc[mf][nf][2], acc[mf][nf][3]);
        }
    }
}

// ---- LN over h + output GEMM + gate; 64 rows/block ----
__global__ __launch_bounds__(256)
void out_kernel(const float* __restrict__ low, const float* __restrict__ lob,
                const float* __restrict__ zb, float* __restrict__ out)
{
    __shared__ float xs[128*66];
    __shared__ float zw_s[16*132];
    __shared__ float mu_s[64], rs_s[64];
    __shared__ float low_s[128], lob_s[128];
    int tid=threadIdx.x;
    int row0 = blockIdx.x*64;
    if (tid<128){ low_s[tid]=low[tid]; lob_s[tid]=lob[tid]; }
    #pragma unroll
    for (int it=0; it<32; ++it){
        int f = tid + it*256;
        int r = f&63, h = f>>6;
        xs[h*66 + r] = g_xt[(size_t)h*NN + row0 + r];
    }
    __syncthreads();
    int lane=tid&31, wid=tid>>5;
    #pragma unroll
    for (int rr=0;rr<8;++rr){
        int r = wid*8+rr;
        float s=0.f,q=0.f;
        #pragma unroll
        for (int m=0;m<4;++m){ float x=xs[(lane+32*m)*66 + r]; s+=x; q+=x*x; }
        #pragma unroll
        for (int o=16;o>0;o>>=1){ s+=__shfl_xor_sync(0xffffffffu,s,o); q+=__shfl_xor_sync(0xffffffffu,q,o); }
        if (lane==0){
            float mu=s*(1.f/128.f), var=q*(1.f/128.f)-mu*mu;
            mu_s[r]=mu; rs_s[r]=rsqrtf(fmaxf(var,0.f)+EPSF);
        }
    }
    __syncthreads();
    int tx=tid&15, ty=tid>>4;
    float acc[4][8];
    #pragma unroll
    for (int u=0;u<4;++u)
        #pragma unroll
        for (int v=0;v<8;++v) acc[u][v]=0.f;
    float mu[4], rs[4];
    #pragma unroll
    for (int u=0;u<4;++u){ mu[u]=mu_s[ty*4+u]; rs[u]=rs_s[ty*4+u]; }
    const float* zwT = g_wT + 5*CH*CH;

    for (int h0=0;h0<CH;h0+=16){
        #pragma unroll
        for (int it=0; it<2; ++it){
            int f=tid+it*256;
            int hh=f>>5, o4=f&31;
            *(float4*)(zw_s + hh*132 + o4*4) = *(const float4*)(zwT + (h0+hh)*CH + o4*4);
        }
        __syncthreads();
        #pragma unroll
        for (int hh=0; hh<16; ++hh){
            int h=h0+hh;
            float lw=low_s[h], lb=lob_s[h];
            float xn[4];
            #pragma unroll
            for (int u=0;u<4;++u) xn[u] = (xs[h*66 + ty*4+u]-mu[u])*rs[u]*lw + lb;
            float w[8];
            *(float4*)(w)   = *(float4*)(zw_s + hh*132 + tx*8);
            *(float4*)(w+4) = *(float4*)(zw_s + hh*132 + tx*8 + 4);
            #pragma unroll
            for (int u=0;u<4;++u)
                #pragma unroll
                for (int v=0;v<8;++v) acc[u][v] += xn[u]*w[v];
        }
        __syncthreads();
    }
    #pragma unroll
    for (int u=0;u<4;++u){
        int grow=row0+ty*4+u;
        const float4* g4 = (const float4*)(g_gate + (size_t)grow*CH + tx*8);
        const float4* b4 = (const float4*)(zb + tx*8);
        float4* o4p = (float4*)(out + (size_t)grow*CH + tx*8);
        #pragma unroll
        for (int w2=0;w2<2;++w2){
            float4 g=g4[w2], b=b4[w2];
            o4p[w2] = make_float4(g.x*(acc[u][w2*4+0]+b.x),
                                  g.y*(acc[u][w2*4+1]+b.y),
                                  g.z*(acc[u][w2*4+2]+b.z),
                                  g.w*(acc[u][w2*4+3]+b.w));
        }
    }
}

extern "C" void kernel_launch(void* const* d_in, const int* in_sizes, int n_in,
                              void* d_out, int out_size) {
    const float* z      = (const float*)d_in[0];
    const float* mask   = (const float*)d_in[1];
    const float* ln_in_w= (const float*)d_in[2];
    const float* ln_in_b= (const float*)d_in[3];
    const float* a_g_w  = (const float*)d_in[4];
    const float* a_g_b  = (const float*)d_in[5];
    const float* a_p_w  = (const float*)d_in[6];
    const float* a_p_b  = (const float*)d_in[7];
    const float* b_g_w  = (const float*)d_in[8];
    const float* b_g_b  = (const float*)d_in[9];
    const float* b_p_w  = (const float*)d_in[10];
    const float* b_p_b  = (const float*)d_in[11];
    const float* g_w    = (const float*)d_in[12];
    const float* g_b    = (const float*)d_in[13];
    const float* ln_out_w=(const float*)d_in[14];
    const float* ln_out_b=(const float*)d_in[15];
    const float* z_w    = (const float*)d_in[16];
    const float* z_b    = (const float*)d_in[17];
    float* out = (float*)d_out;

    cudaFuncSetAttribute(projmma_kernel, cudaFuncAttributeMaxDynamicSharedMemorySize, 51200);

    transpose128<<<dim3(4,4), dim3(32,8)>>>(z_w, 5);
    wsplit_kernel<<<5,256>>>(a_g_w, a_p_w, b_g_w, b_p_w, g_w);
    ln_split_kernel<<<NN/8,256>>>(z, ln_in_w, ln_in_b);
    projmma_kernel<<<dim3(2304,3),256,51200>>>(mask, a_g_b, a_p_b, b_g_b, b_p_b, g_b);
    tri_mma_kernel<<<dim3(3,3,CH),256>>>();
    out_kernel<<<NN/64,256>>>(ln_out_w, ln_out_b, z_b, out);
}

// round 8
// speedup vs baseline: 3.5206x; 1.1388x over previous
#include <cuda_runtime.h>
#include <cuda_bf16.h>
#include <cstdint>

#define NRES 384
#define CH 128
#define NN (NRES*NRES)
#define EPSF 1e-5f
#define KSPLIT (3*NRES)   // 1152 (triangle K')
#define KP 384            // proj/out K' = 3*128
#define BKP 32
#define NCHP (KP/BKP)     // 12

// ---- scratch (device globals; no allocation) ----
__device__ __nv_bfloat16 g_as[(size_t)CH*NRES*KSPLIT];
__device__ __nv_bfloat16 g_bs[(size_t)CH*NRES*KSPLIT];
__device__ __nv_bfloat16 g_zs[(size_t)NN*KP];
__device__ __nv_bfloat16 g_xs[(size_t)NN*KP];
__device__ __nv_bfloat16 g_ws[(size_t)6*CH*KP];
__device__ float g_gate[(size_t)NN*CH];
__device__ float g_xt[(size_t)CH*NN];

__device__ __forceinline__ float sigf(float x){ return 1.f/(1.f+__expf(-x)); }

__device__ __forceinline__ uint32_t s2u(const void* p){
    uint32_t a;
    asm("{ .reg .u64 t; cvta.to.shared.u64 t, %1; cvt.u32.u64 %0, t; }" : "=r"(a) : "l"(p));
    return a;
}
__device__ __forceinline__ void ldsm4(uint32_t &r0,uint32_t &r1,uint32_t &r2,uint32_t &r3,uint32_t a){
    asm volatile("ldmatrix.sync.aligned.m8n8.x4.shared.b16 {%0,%1,%2,%3}, [%4];"
        : "=r"(r0),"=r"(r1),"=r"(r2),"=r"(r3) : "r"(a));
}
__device__ __forceinline__ void mma16816(float* d, const uint32_t* a, const uint32_t* b){
    asm volatile("mma.sync.aligned.m16n8k16.row.col.f32.bf16.bf16.f32 "
        "{%0,%1,%2,%3}, {%4,%5,%6,%7}, {%8,%9}, {%0,%1,%2,%3};"
        : "+f"(d[0]),"+f"(d[1]),"+f"(d[2]),"+f"(d[3])
        : "r"(a[0]),"r"(a[1]),"r"(a[2]),"r"(a[3]), "r"(b[0]),"r"(b[1]));
}
__device__ __forceinline__ void cpa(uint32_t d, const void* s){
    asm volatile("cp.async.ca.shared.global [%0], [%1], 16;" :: "r"(d), "l"(s) : "memory");
}
__device__ __forceinline__ void cp_commit(){ asm volatile("cp.async.commit_group;" ::: "memory"); }
template<int N> __device__ __forceinline__ void cp_wait(){ asm volatile("cp.async.wait_group %0;" :: "n"(N) : "memory"); }

// ---- split 6 weights into bf16 [Wh|Wh|Wl], K-major rows ----
__global__ void wsplit_kernel(const float* w0, const float* w1, const float* w2,
                              const float* w3, const float* w4, const float* w5){
    const float* srcs[6] = {w0,w1,w2,w3,w4,w5};
    const float* W = srcs[blockIdx.x];
    __nv_bfloat16* dst = g_ws + (size_t)blockIdx.x*CH*KP;
    for (int it=0; it<64; ++it){
        int idx = threadIdx.x + it*256;
        int o = idx>>7, k = idx&127;
        float v = W[idx];
        __nv_bfloat16 hi = __float2bfloat16(v);
        __nv_bfloat16 lo = __float2bfloat16(v - __bfloat162float(hi));
        dst[(size_t)o*KP + k]       = hi;
        dst[(size_t)o*KP + 128 + k] = hi;
        dst[(size_t)o*KP + 256 + k] = lo;
    }
}

// ---- LN(z) -> split bf16 rows [zh|zl|zh] ----
__global__ __launch_bounds__(256)
void ln_split_kernel(const float* __restrict__ z,
                     const float* __restrict__ lnw, const float* __restrict__ lnb){
    int tid=threadIdx.x, wid=tid>>5, lane=tid&31;
    size_t row = (size_t)blockIdx.x*8 + wid;
    float4 v = *(const float4*)(z + row*CH + lane*4);
    float s = v.x+v.y+v.z+v.w;
    float q = v.x*v.x+v.y*v.y+v.z*v.z+v.w*v.w;
    #pragma unroll
    for (int o=16;o>0;o>>=1){ s+=__shfl_xor_sync(0xffffffffu,s,o); q+=__shfl_xor_sync(0xffffffffu,q,o); }
    float mu=s*(1.f/128.f), var=q*(1.f/128.f)-mu*mu;
    float rs=rsqrtf(fmaxf(var,0.f)+EPSF);
    float4 w4 = *(const float4*)(lnw + lane*4);
    float4 b4 = *(const float4*)(lnb + lane*4);
    float n[4] = {(v.x-mu)*rs*w4.x+b4.x, (v.y-mu)*rs*w4.y+b4.y,
                  (v.z-mu)*rs*w4.z+b4.z, (v.w-mu)*rs*w4.w+b4.w};
    __nv_bfloat16 hi[4], lo[4];
    #pragma unroll
    for (int j=0;j<4;++j){
        hi[j] = __float2bfloat16(n[j]);
        lo[j] = __float2bfloat16(n[j]-__bfloat162float(hi[j]));
    }
    __nv_bfloat16* d = g_zs + row*KP + lane*4;
    *(__nv_bfloat162*)(d)       = __nv_bfloat162{hi[0],hi[1]};
    *(__nv_bfloat162*)(d+2)     = __nv_bfloat162{hi[2],hi[3]};
    *(__nv_bfloat162*)(d+128)   = __nv_bfloat162{lo[0],lo[1]};
    *(__nv_bfloat162*)(d+130)   = __nv_bfloat162{lo[2],lo[3]};
    *(__nv_bfloat162*)(d+256)   = __nv_bfloat162{hi[0],hi[1]};
    *(__nv_bfloat162*)(d+258)   = __nv_bfloat162{hi[2],hi[3]};
}

// ---- proj on tensor cores: 64-row tiles, grid (2304, 3) ----
#define LDP 40
#define ABUF 5120u
#define WBUF 10240u
#define STEP 25600u

__device__ __forceinline__ void proj_issue(int tid, int c, int buf, bool hasP,
    uint32_t sA, uint32_t sG, uint32_t sP,
    const __nv_bfloat16* Az, const __nv_bfloat16* WG, const __nv_bfloat16* WP){
    uint32_t bofs = (uint32_t)buf*STEP;
    {
        int row = tid>>2, seg = tid&3;
        cpa(sA + bofs + (uint32_t)(row*80 + seg*16), Az + (size_t)row*KP + c*BKP + seg*8);
    }
    #pragma unroll
    for (int it=0; it<2; ++it){
        int idx = tid + it*256;
        int row = idx>>2, seg = idx&3;
        uint32_t off = bofs + (uint32_t)(row*80 + seg*16);
        size_t gof = (size_t)row*KP + c*BKP + seg*8;
        cpa(sG + off, WG + gof);
        if (hasP) cpa(sP + off, WP + gof);
    }
    cp_commit();
}

__global__ __launch_bounds__(256,2)
void projmma_kernel(const float* __restrict__ mask_,
                    const float* __restrict__ agb, const float* __restrict__ apb,
                    const float* __restrict__ bgb, const float* __restrict__ bpb,
                    const float* __restrict__ gb_)
{
    extern __shared__ char sm[];
    uint32_t sA = s2u(sm);
    uint32_t sG = sA + ABUF;
    uint32_t sP = sG + WBUF;
    float* ot = (float*)sm;

    int tid=threadIdx.x, wid=tid>>5, lane=tid&31;
    int wm=wid&1, wn=wid>>1;
    int t2 = blockIdx.x, ph = blockIdx.y;
    bool hasP = ph<2;
    const __nv_bfloat16* WG = g_ws + (size_t)(hasP ? 2*ph : 4)*CH*KP;
    const __nv_bfloat16* WP = g_ws + (size_t)(hasP ? 2*ph+1 : 4)*CH*KP;
    const float* GBp = (ph==0)?agb:((ph==1)?bgb:gb_);
    const float* PBp = (ph==0)?apb:bpb;
    const __nv_bfloat16* Az = g_zs + (size_t)t2*64*KP;

    float accG[2][4][4], accP[2][4][4];
    #pragma unroll
    for (int mf=0;mf<2;++mf)
        #pragma unroll
        for (int nf=0;nf<4;++nf)
            #pragma unroll
            for (int r=0;r<4;++r){ accG[mf][nf][r]=0.f; accP[mf][nf][r]=0.f; }

    proj_issue(tid, 0, 0, hasP, sA, sG, sP, Az, WG, WP);

    for (int c=0; c<NCHP; ++c){
        int buf = c & 1;
        if (c+1<NCHP){ proj_issue(tid, c+1, buf^1, hasP, sA, sG, sP, Az, WG, WP); cp_wait<1>(); }
        else cp_wait<0>();
        __syncthreads();
        uint32_t bofs = (uint32_t)buf*STEP;
        #pragma unroll
        for (int ks=0; ks<2; ++ks){
            uint32_t a[2][4];
            #pragma unroll
            for (int mf=0; mf<2; ++mf){
                int row = wm*32 + mf*16 + (lane&15);
                int kc  = ks*16 + (lane>>4)*8;
                ldsm4(a[mf][0],a[mf][1],a[mf][2],a[mf][3], sA + bofs + (uint32_t)(row*LDP + kc)*2);
            }
            uint32_t bg[4][2], bp[4][2];
            #pragma unroll
            for (int nf2=0; nf2<2; ++nf2){
                int nrow = wn*32 + nf2*16 + (lane&7) + ((lane>>4)<<3);
                int kc   = ks*16 + ((lane>>3)&1)*8;
                uint32_t r0,r1,r2,r3;
                ldsm4(r0,r1,r2,r3, sG + bofs + (uint32_t)(nrow*LDP + kc)*2);
                bg[nf2*2+0][0]=r0; bg[nf2*2+0][1]=r1; bg[nf2*2+1][0]=r2; bg[nf2*2+1][1]=r3;
                if (hasP){
                    ldsm4(r0,r1,r2,r3, sP + bofs + (uint32_t)(nrow*LDP + kc)*2);
                    bp[nf2*2+0][0]=r0; bp[nf2*2+0][1]=r1; bp[nf2*2+1][0]=r2; bp[nf2*2+1][1]=r3;
                }
            }
            #pragma unroll
            for (int mf=0; mf<2; ++mf)
                #pragma unroll
                for (int nf=0; nf<4; ++nf){
                    mma16816(accG[mf][nf], a[mf], bg[nf]);
                    if (hasP) mma16816(accP[mf][nf], a[mf], bp[nf]);
                }
        }
        __syncthreads();
    }

    if (hasP){
        __nv_bfloat16* dst = ph ? g_bs : g_as;
        int i_idx = t2/6, k0 = (t2%6)*64;
        #pragma unroll
        for (int mf=0; mf<2; ++mf)
            #pragma unroll
            for (int nf=0; nf<4; ++nf){
                int col = wn*32 + nf*8 + (lane&3)*2;
                int row = wm*32 + mf*16 + (lane>>2);
                float mk0 = __ldg(mask_ + t2*64 + row);
                float mk1 = __ldg(mask_ + t2*64 + row + 8);
                float g0=__ldg(GBp+col), g1=__ldg(GBp+col+1);
                float p0=__ldg(PBp+col), p1=__ldg(PBp+col+1);
                ot[col*68+row]       = mk0*sigf(accG[mf][nf][0]+g0)*(accP[mf][nf][0]+p0);
                ot[(col+1)*68+row]   = mk0*sigf(accG[mf][nf][1]+g1)*(accP[mf][nf][1]+p1);
                ot[col*68+row+8]     = mk1*sigf(accG[mf][nf][2]+g0)*(accP[mf][nf][2]+p0);
                ot[(col+1)*68+row+8] = mk1*sigf(accG[mf][nf][3]+g1)*(accP[mf][nf][3]+p1);
            }
        __syncthreads();
        #pragma unroll
        for (int it2=0; it2<32; ++it2){
            int f = tid + it2*256;
            int r = f&63, o = f>>6;
            float v = ot[o*68 + r];
            __nv_bfloat16 hi = __float2bfloat16(v);
            __nv_bfloat16 lo = __float2bfloat16(v - __bfloat162float(hi));
            size_t base = (size_t)o*(NRES*KSPLIT) + (size_t)i_idx*KSPLIT + (k0 + r);
            if (ph==0){ dst[base]=hi; dst[base+NRES]=lo; dst[base+2*NRES]=hi; }
            else      { dst[base]=hi; dst[base+NRES]=hi; dst[base+2*NRES]=lo; }
        }
    } else {
        #pragma unroll
        for (int mf=0; mf<2; ++mf)
            #pragma unroll
            for (int nf=0; nf<4; ++nf){
                int col = wn*32 + nf*8 + (lane&3)*2;
                int row = wm*32 + mf*16 + (lane>>2);
                size_t R0 = (size_t)t2*64 + row;
                float g0=__ldg(GBp+col), g1=__ldg(GBp+col+1);
                *(float2*)(g_gate + R0*CH + col) =
                    make_float2(sigf(accG[mf][nf][0]+g0), sigf(accG[mf][nf][1]+g1));
                *(float2*)(g_gate + (R0+8)*CH + col) =
                    make_float2(sigf(accG[mf][nf][2]+g0), sigf(accG[mf][nf][3]+g1));
            }
    }
}

// ---- triangle GEMM on mma.sync bf16, cp.async double-buffered ----
#define BK 32
#define LDA 40
#define NCH (KSPLIT/BK)
#define TBUF 10240u

__device__ __forceinline__ void tri_issue(int tid, int c, int buf,
    const __nv_bfloat16* Ag, const __nv_bfloat16* Bg, uint32_t sAb, uint32_t sBb){
    int lrow = tid>>2, lsub = tid&3;
    #pragma unroll
    for (int half=0; half<2; ++half){
        int row = lrow + half*64;
        uint32_t off = (uint32_t)buf*TBUF + (uint32_t)(row*80 + lsub*16);
        cpa(sAb + off, Ag + (size_t)row*KSPLIT + c*BK + lsub*8);
        cpa(sBb + off, Bg + (size_t)row*KSPLIT + c*BK + lsub*8);
    }
    cp_commit();
}

__global__ __launch_bounds__(256,2)
void tri_mma_kernel(){
    __shared__ __nv_bfloat16 As[2][128*LDA];
    __shared__ __nv_bfloat16 Bs[2][128*LDA];

    int tid = threadIdx.x;
    int wid = tid>>5, lane = tid&31;
    int wm = wid & 1, wn = wid >> 1;
    int h = blockIdx.z, i0 = blockIdx.y*128, j0 = blockIdx.x*128;

    const __nv_bfloat16* Ag = g_as + ((size_t)h*NRES + i0)*KSPLIT;
    const __nv_bfloat16* Bg = g_bs + ((size_t)h*NRES + j0)*KSPLIT;
    uint32_t sAb = s2u(&As[0][0]);
    uint32_t sBb = s2u(&Bs[0][0]);

    float acc[4][4][4];
    #pragma unroll
    for (int mf=0;mf<4;++mf)
        #pragma unroll
        for (int nf=0;nf<4;++nf)
            #pragma unroll
            for (int r=0;r<4;++r) acc[mf][nf][r]=0.f;

    tri_issue(tid, 0, 0, Ag, Bg, sAb, sBb);

    for (int c=0; c<NCH; ++c){
        int buf = c & 1;
        if (c+1 < NCH){ tri_issue(tid, c+1, buf^1, Ag, Bg, sAb, sBb); cp_wait<1>(); }
        else cp_wait<0>();
        __syncthreads();
        uint32_t as_base = sAb + (uint32_t)buf*TBUF;
        uint32_t bs_base = sBb + (uint32_t)buf*TBUF;
        #pragma unroll
        for (int ks=0; ks<2; ++ks){
            uint32_t a[4][4];
            #pragma unroll
            for (int mf=0; mf<4; ++mf){
                int row = wm*64 + mf*16 + (lane&15);
                int kc  = ks*16 + (lane>>4)*8;
                ldsm4(a[mf][0],a[mf][1],a[mf][2],a[mf][3], as_base + (uint32_t)(row*LDA + kc)*2);
            }
            uint32_t b[4][2];
            #pragma unroll
            for (int nf2=0; nf2<2; ++nf2){
                int nrow = wn*32 + nf2*16 + (lane&7) + ((lane>>4)<<3);
                int kc   = ks*16 + ((lane>>3)&1)*8;
                uint32_t r0,r1,r2,r3;
                ldsm4(r0,r1,r2,r3, bs_base + (uint32_t)(nrow*LDA + kc)*2);
                b[nf2*2+0][0]=r0; b[nf2*2+0][1]=r1;
                b[nf2*2+1][0]=r2; b[nf2*2+1][1]=r3;
            }
            #pragma unroll
            for (int mf=0; mf<4; ++mf)
                #pragma unroll
                for (int nf=0; nf<4; ++nf)
                    mma16816(acc[mf][nf], a[mf], b[nf]);
        }
        __syncthreads();
    }

    float* X = g_xt + (size_t)h*NN;
    #pragma unroll
    for (int mf=0; mf<4; ++mf){
        #pragma unroll
        for (int nf=0; nf<4; ++nf){
            int row = i0 + wm*64 + mf*16 + (lane>>2);
            int col = j0 + wn*32 + nf*8 + (lane&3)*2;
            *(float2*)(X + (size_t)row*NRES + col)     = make_float2(acc[mf][nf][0], acc[mf][nf][1]);
            *(float2*)(X + (size_t)(row+8)*NRES + col) = make_float2(acc[mf][nf][2], acc[mf][nf][3]);
        }
    }
}

// ---- LN over h of x -> split bf16 rows [xh|xl|xh] ----
__global__ __launch_bounds__(256)
void ln_out_split_kernel(const float* __restrict__ low, const float* __restrict__ lob){
    __shared__ float xs[128*66];
    __shared__ float mu_s[64], rs_s[64];
    __shared__ float low_s[128], lob_s[128];
    int tid=threadIdx.x;
    int row0 = blockIdx.x*64;
    if (tid<128){ low_s[tid]=low[tid]; lob_s[tid]=lob[tid]; }
    #pragma unroll
    for (int it=0; it<32; ++it){
        int f = tid + it*256;
        int r = f&63, h = f>>6;
        xs[h*66 + r] = g_xt[(size_t)h*NN + row0 + r];
    }
    __syncthreads();
    int lane=tid&31, wid=tid>>5;
    #pragma unroll
    for (int rr=0;rr<8;++rr){
        int r = wid*8+rr;
        float s=0.f,q=0.f;
        #pragma unroll
        for (int m=0;m<4;++m){ float x=xs[(lane+32*m)*66 + r]; s+=x; q+=x*x; }
        #pragma unroll
        for (int o=16;o>0;o>>=1){ s+=__shfl_xor_sync(0xffffffffu,s,o); q+=__shfl_xor_sync(0xffffffffu,q,o); }
        if (lane==0){
            float mu=s*(1.f/128.f), var=q*(1.f/128.f)-mu*mu;
            mu_s[r]=mu; rs_s[r]=rsqrtf(fmaxf(var,0.f)+EPSF);
        }
    }
    __syncthreads();
    #pragma unroll
    for (int it=0; it<16; ++it){
        int f = tid + it*256;
        int r = f>>6, h2 = (f&63)*2;
        float mu=mu_s[r], rs=rs_s[r];
        float x0 = (xs[(h2+0)*66+r]-mu)*rs*low_s[h2+0]+lob_s[h2+0];
        float x1 = (xs[(h2+1)*66+r]-mu)*rs*low_s[h2+1]+lob_s[h2+1];
        __nv_bfloat16 h0=__float2bfloat16(x0), h1=__float2bfloat16(x1);
        __nv_bfloat16 l0=__float2bfloat16(x0-__bfloat162float(h0));
        __nv_bfloat16 l1=__float2bfloat16(x1-__bfloat162float(h1));
        __nv_bfloat16* d = g_xs + (size_t)(row0+r)*KP + h2;
        *(__nv_bfloat162*)(d)     = __nv_bfloat162{h0,h1};
        *(__nv_bfloat162*)(d+128) = __nv_bfloat162{l0,l1};
        *(__nv_bfloat162*)(d+256) = __nv_bfloat162{h0,h1};
    }
}

// ---- out GEMM on tensor cores: out = gate * (xn @ z_w^T + z_b) ----
#define OSTEP 15360u   // ABUF + WBUF

__device__ __forceinline__ void out_issue(int tid, int c, int buf,
    uint32_t sA, uint32_t sB, const __nv_bfloat16* Ax, const __nv_bfloat16* W){
    uint32_t bofs = (uint32_t)buf*OSTEP;
    {
        int row = tid>>2, seg = tid&3;
        cpa(sA + bofs + (uint32_t)(row*80 + seg*16), Ax + (size_t)row*KP + c*BKP + seg*8);
    }
    #pragma unroll
    for (int it=0; it<2; ++it){
        int idx = tid + it*256;
        int row = idx>>2, seg = idx&3;
        cpa(sB + bofs + (uint32_t)(row*80 + seg*16), W + (size_t)row*KP + c*BKP + seg*8);
    }
    cp_commit();
}

__global__ __launch_bounds__(256,2)
void outmma_kernel(const float* __restrict__ zb, float* __restrict__ out)
{
    extern __shared__ char sm[];
    uint32_t sA = s2u(sm);
    uint32_t sB = sA + ABUF;

    int tid=threadIdx.x, wid=tid>>5, lane=tid&31;
    int wm=wid&1, wn=wid>>1;
    int t2 = blockIdx.x;
    const __nv_bfloat16* W = g_ws + (size_t)5*CH*KP;
    const __nv_bfloat16* Ax = g_xs + (size_t)t2*64*KP;

    float acc[2][4][4];
    #pragma unroll
    for (int mf=0;mf<2;++mf)
        #pragma unroll
        for (int nf=0;nf<4;++nf)
            #pragma unroll
            for (int r=0;r<4;++r) acc[mf][nf][r]=0.f;

    out_issue(tid, 0, 0, sA, sB, Ax, W);

    for (int c=0; c<NCHP; ++c){
        int buf = c & 1;
        if (c+1<NCHP){ out_issue(tid, c+1, buf^1, sA, sB, Ax, W); cp_wait<1>(); }
        else cp_wait<0>();
        __syncthreads();
        uint32_t bofs = (uint32_t)buf*OSTEP;
        #pragma unroll
        for (int ks=0; ks<2; ++ks){
            uint32_t a[2][4];
            #pragma unroll
            for (int mf=0; mf<2; ++mf){
                int row = wm*32 + mf*16 + (lane&15);
                int kc  = ks*16 + (lane>>4)*8;
                ldsm4(a[mf][0],a[mf][1],a[mf][2],a[mf][3], sA + bofs + (uint32_t)(row*LDP + kc)*2);
            }
            uint32_t b[4][2];
            #pragma unroll
            for (int nf2=0; nf2<2; ++nf2){
                int nrow = wn*32 + nf2*16 + (lane&7) + ((lane>>4)<<3);
                int kc   = ks*16 + ((lane>>3)&1)*8;
                uint32_t r0,r1,r2,r3;
                ldsm4(r0,r1,r2,r3, sB + bofs + (uint32_t)(nrow*LDP + kc)*2);
                b[nf2*2+0][0]=r0; b[nf2*2+0][1]=r1;
                b[nf2*2+1][0]=r2; b[nf2*2+1][1]=r3;
            }
            #pragma unroll
            for (int mf=0; mf<2; ++mf)
                #pragma unroll
                for (int nf=0; nf<4; ++nf)
                    mma16816(acc[mf][nf], a[mf], b[nf]);
        }
        __syncthreads();
    }

    #pragma unroll
    for (int mf=0; mf<2; ++mf)
        #pragma unroll
        for (int nf=0; nf<4; ++nf){
            int col = wn*32 + nf*8 + (lane&3)*2;
            int row = wm*32 + mf*16 + (lane>>2);
            size_t R0 = (size_t)t2*64 + row;
            float2 zb2 = *(const float2*)(zb + col);
            float2 ga = *(const float2*)(g_gate + R0*CH + col);
            float2 gb2 = *(const float2*)(g_gate + (R0+8)*CH + col);
            *(float2*)(out + R0*CH + col) =
                make_float2(ga.x*(acc[mf][nf][0]+zb2.x), ga.y*(acc[mf][nf][1]+zb2.y));
            *(float2*)(out + (R0+8)*CH + col) =
                make_float2(gb2.x*(acc[mf][nf][2]+zb2.x), gb2.y*(acc[mf][nf][3]+zb2.y));
        }
}

extern "C" void kernel_launch(void* const* d_in, const int* in_sizes, int n_in,
                              void* d_out, int out_size) {
    const float* z      = (const float*)d_in[0];
    const float* mask   = (const float*)d_in[1];
    const float* ln_in_w= (const float*)d_in[2];
    const float* ln_in_b= (const float*)d_in[3];
    const float* a_g_w  = (const float*)d_in[4];
    const float* a_g_b  = (const float*)d_in[5];
    const float* a_p_w  = (const float*)d_in[6];
    const float* a_p_b  = (const float*)d_in[7];
    const float* b_g_w  = (const float*)d_in[8];
    const float* b_g_b  = (const float*)d_in[9];
    const float* b_p_w  = (const float*)d_in[10];
    const float* b_p_b  = (const float*)d_in[11];
    const float* g_w    = (const float*)d_in[12];
    const float* g_b    = (const float*)d_in[13];
    const float* ln_out_w=(const float*)d_in[14];
    const float* ln_out_b=(const float*)d_in[15];
    const float* z_w    = (const float*)d_in[16];
    const float* z_b    = (const float*)d_in[17];
    float* out = (float*)d_out;

    cudaFuncSetAttribute(projmma_kernel, cudaFuncAttributeMaxDynamicSharedMemorySize, 51200);
    cudaFuncSetAttribute(outmma_kernel, cudaFuncAttributeMaxDynamicSharedMemorySize, 30720);

    wsplit_kernel<<<6,256>>>(a_g_w, a_p_w, b_g_w, b_p_w, g_w, z_w);
    ln_split_kernel<<<NN/8,256>>>(z, ln_in_w, ln_in_b);
    projmma_kernel<<<dim3(2304,3),256,51200>>>(mask, a_g_b, a_p_b, b_g_b, b_p_b, g_b);
    tri_mma_kernel<<<dim3(3,3,CH),256>>>();
    ln_out_split_kernel<<<NN/64,256>>>(ln_out_w, ln_out_b);
    outmma_kernel<<<NN/64,256,30720>>>(z_b, out);
}

// round 9
// speedup vs baseline: 3.9654x; 1.1263x over previous
#include <cuda_runtime.h>
#include <cuda_bf16.h>
#include <cstdint>

#define NRES 384
#define CH 128
#define NN (NRES*NRES)
#define EPSF 1e-5f
#define KS2 768           // triangle operand row: [hi(384)|lo(384)]
#define KP2 256           // proj/out row: [hi(128)|lo(128)]
#define BK 32

// ---- scratch (device globals; no allocation) ----
__device__ __nv_bfloat16 g_as[(size_t)CH*NRES*KS2];
__device__ __nv_bfloat16 g_bs[(size_t)CH*NRES*KS2];
__device__ __nv_bfloat16 g_zs[(size_t)NN*KP2];
__device__ __nv_bfloat16 g_xs[(size_t)NN*KP2];
__device__ __nv_bfloat16 g_ws[(size_t)6*CH*KP2];
__device__ float g_gate[(size_t)NN*CH];
__device__ float g_xt[(size_t)CH*NN];

__device__ __forceinline__ float sigf(float x){ return 1.f/(1.f+__expf(-x)); }

__device__ __forceinline__ uint32_t s2u(const void* p){
    uint32_t a;
    asm("{ .reg .u64 t; cvta.to.shared.u64 t, %1; cvt.u32.u64 %0, t; }" : "=r"(a) : "l"(p));
    return a;
}
__device__ __forceinline__ void ldsm4(uint32_t &r0,uint32_t &r1,uint32_t &r2,uint32_t &r3,uint32_t a){
    asm volatile("ldmatrix.sync.aligned.m8n8.x4.shared.b16 {%0,%1,%2,%3}, [%4];"
        : "=r"(r0),"=r"(r1),"=r"(r2),"=r"(r3) : "r"(a));
}
__device__ __forceinline__ void mma16816(float* d, const uint32_t* a, const uint32_t* b){
    asm volatile("mma.sync.aligned.m16n8k16.row.col.f32.bf16.bf16.f32 "
        "{%0,%1,%2,%3}, {%4,%5,%6,%7}, {%8,%9}, {%0,%1,%2,%3};"
        : "+f"(d[0]),"+f"(d[1]),"+f"(d[2]),"+f"(d[3])
        : "r"(a[0]),"r"(a[1]),"r"(a[2]),"r"(a[3]), "r"(b[0]),"r"(b[1]));
}
__device__ __forceinline__ void cpa(uint32_t d, const void* s){
    asm volatile("cp.async.ca.shared.global [%0], [%1], 16;" :: "r"(d), "l"(s) : "memory");
}
__device__ __forceinline__ void cp_commit(){ asm volatile("cp.async.commit_group;" ::: "memory"); }
template<int N> __device__ __forceinline__ void cp_wait(){ asm volatile("cp.async.wait_group %0;" :: "n"(N) : "memory"); }

// load 4 n8k16 B fragments (32 n-rows) from padded smem (40 bf16/row)
__device__ __forceinline__ void ldB(uint32_t base, int wn, int lane, int ks, uint32_t bf[4][2]){
    int kc = ks*16 + ((lane>>3)&1)*8;
    #pragma unroll
    for (int nf2=0; nf2<2; ++nf2){
        int nrow = wn*32 + nf2*16 + (lane&7) + ((lane>>4)<<3);
        uint32_t r0,r1,r2,r3;
        ldsm4(r0,r1,r2,r3, base + (uint32_t)(nrow*40 + kc)*2);
        bf[nf2*2+0][0]=r0; bf[nf2*2+0][1]=r1;
        bf[nf2*2+1][0]=r2; bf[nf2*2+1][1]=r3;
    }
}

// ---- split 6 weights into bf16 [Wh|Wl] ----
__global__ void wsplit_kernel(const float* w0, const float* w1, const float* w2,
                              const float* w3, const float* w4, const float* w5){
    const float* srcs[6] = {w0,w1,w2,w3,w4,w5};
    const float* W = srcs[blockIdx.x];
    __nv_bfloat16* dst = g_ws + (size_t)blockIdx.x*CH*KP2;
    for (int it=0; it<64; ++it){
        int idx = threadIdx.x + it*256;
        int o = idx>>7, k = idx&127;
        float v = W[idx];
        __nv_bfloat16 hi = __float2bfloat16(v);
        __nv_bfloat16 lo = __float2bfloat16(v - __bfloat162float(hi));
        dst[(size_t)o*KP2 + k]       = hi;
        dst[(size_t)o*KP2 + 128 + k] = lo;
    }
}

// ---- LN(z) -> split bf16 rows [zh|zl] ----
__global__ __launch_bounds__(256)
void ln_split_kernel(const float* __restrict__ z,
                     const float* __restrict__ lnw, const float* __restrict__ lnb){
    int tid=threadIdx.x, wid=tid>>5, lane=tid&31;
    size_t row = (size_t)blockIdx.x*8 + wid;
    float4 v = *(const float4*)(z + row*CH + lane*4);
    float s = v.x+v.y+v.z+v.w;
    float q = v.x*v.x+v.y*v.y+v.z*v.z+v.w*v.w;
    #pragma unroll
    for (int o=16;o>0;o>>=1){ s+=__shfl_xor_sync(0xffffffffu,s,o); q+=__shfl_xor_sync(0xffffffffu,q,o); }
    float mu=s*(1.f/128.f), var=q*(1.f/128.f)-mu*mu;
    float rs=rsqrtf(fmaxf(var,0.f)+EPSF);
    float4 w4 = *(const float4*)(lnw + lane*4);
    float4 b4 = *(const float4*)(lnb + lane*4);
    float n[4] = {(v.x-mu)*rs*w4.x+b4.x, (v.y-mu)*rs*w4.y+b4.y,
                  (v.z-mu)*rs*w4.z+b4.z, (v.w-mu)*rs*w4.w+b4.w};
    __nv_bfloat16 hi[4], lo[4];
    #pragma unroll
    for (int j=0;j<4;++j){
        hi[j] = __float2bfloat16(n[j]);
        lo[j] = __float2bfloat16(n[j]-__bfloat162float(hi[j]));
    }
    __nv_bfloat16* d = g_zs + row*KP2 + lane*4;
    *(__nv_bfloat162*)(d)     = __nv_bfloat162{hi[0],hi[1]};
    *(__nv_bfloat162*)(d+2)   = __nv_bfloat162{hi[2],hi[3]};
    *(__nv_bfloat162*)(d+128) = __nv_bfloat162{lo[0],lo[1]};
    *(__nv_bfloat162*)(d+130) = __nv_bfloat162{lo[2],lo[3]};
}

// ================= projmma: 64-row tiles, grid (2304,3) =================
// terms: zh*Wh + zl*Wh + zh*Wl, all within each 32-K chunk
// stage regions (bytes): Ah 0, Al 5120, Gh 10240, Gl 20480, Ph 30720, Pl 40960
#define PSTEP 51200u
#define NCH_P 4

__device__ __forceinline__ void proj_issue(int tid, int c, int buf, bool hasP,
    uint32_t sb, const __nv_bfloat16* Az, const __nv_bfloat16* WG, const __nv_bfloat16* WP){
    uint32_t bofs = (uint32_t)buf*PSTEP;
    {
        int row = tid>>2, seg = tid&3;
        uint32_t off = bofs + (uint32_t)(row*80 + seg*16);
        const __nv_bfloat16* ar = Az + (size_t)row*KP2 + c*BK + seg*8;
        cpa(sb + off, ar);            // zh
        cpa(sb + 5120u + off, ar+128);// zl
    }
    #pragma unroll
    for (int it=0; it<2; ++it){
        int idx = tid + it*256;
        int row = idx>>2, seg = idx&3;
        uint32_t off = bofs + (uint32_t)(row*80 + seg*16);
        const __nv_bfloat16* gr = WG + (size_t)row*KP2 + c*BK + seg*8;
        cpa(sb + 10240u + off, gr);
        cpa(sb + 20480u + off, gr+128);
        if (hasP){
            const __nv_bfloat16* pr = WP + (size_t)row*KP2 + c*BK + seg*8;
            cpa(sb + 30720u + off, pr);
            cpa(sb + 40960u + off, pr+128);
        }
    }
    cp_commit();
}

__global__ __launch_bounds__(256,2)
void projmma_kernel(const float* __restrict__ mask_,
                    const float* __restrict__ agb, const float* __restrict__ apb,
                    const float* __restrict__ bgb, const float* __restrict__ bpb,
                    const float* __restrict__ gb_)
{
    extern __shared__ char sm[];
    uint32_t sb = s2u(sm);
    float* ot = (float*)sm;

    int tid=threadIdx.x, wid=tid>>5, lane=tid&31;
    int wm=wid&1, wn=wid>>1;
    int t2 = blockIdx.x, ph = blockIdx.y;
    bool hasP = ph<2;
    const __nv_bfloat16* WG = g_ws + (size_t)(hasP ? 2*ph : 4)*CH*KP2;
    const __nv_bfloat16* WP = g_ws + (size_t)(hasP ? 2*ph+1 : 4)*CH*KP2;
    const float* GBp = (ph==0)?agb:((ph==1)?bgb:gb_);
    const float* PBp = (ph==0)?apb:bpb;
    const __nv_bfloat16* Az = g_zs + (size_t)t2*64*KP2;

    float accG[2][4][4], accP[2][4][4];
    #pragma unroll
    for (int mf=0;mf<2;++mf)
        #pragma unroll
        for (int nf=0;nf<4;++nf)
            #pragma unroll
            for (int r=0;r<4;++r){ accG[mf][nf][r]=0.f; accP[mf][nf][r]=0.f; }

    proj_issue(tid, 0, 0, hasP, sb, Az, WG, WP);

    for (int c=0; c<NCH_P; ++c){
        int buf = c & 1;
        if (c+1<NCH_P){ proj_issue(tid, c+1, buf^1, hasP, sb, Az, WG, WP); cp_wait<1>(); }
        else cp_wait<0>();
        __syncthreads();
        uint32_t bofs = sb + (uint32_t)buf*PSTEP;
        #pragma unroll
        for (int ks=0; ks<2; ++ks){
            uint32_t ah[2][4], al[2][4];
            #pragma unroll
            for (int mf=0; mf<2; ++mf){
                int row = wm*32 + mf*16 + (lane&15);
                int kc  = ks*16 + (lane>>4)*8;
                uint32_t ro = (uint32_t)(row*40 + kc)*2;
                ldsm4(ah[mf][0],ah[mf][1],ah[mf][2],ah[mf][3], bofs + ro);
                ldsm4(al[mf][0],al[mf][1],al[mf][2],al[mf][3], bofs + 5120u + ro);
            }
            uint32_t bf[4][2];
            ldB(bofs + 10240u, wn, lane, ks, bf);   // Gh
            #pragma unroll
            for (int mf=0; mf<2; ++mf)
                #pragma unroll
                for (int nf=0; nf<4; ++nf){
                    mma16816(accG[mf][nf], ah[mf], bf[nf]);
                    mma16816(accG[mf][nf], al[mf], bf[nf]);
                }
            ldB(bofs + 20480u, wn, lane, ks, bf);   // Gl
            #pragma unroll
            for (int mf=0; mf<2; ++mf)
                #pragma unroll
                for (int nf=0; nf<4; ++nf)
                    mma16816(accG[mf][nf], ah[mf], bf[nf]);
            if (hasP){
                ldB(bofs + 30720u, wn, lane, ks, bf);  // Ph
                #pragma unroll
                for (int mf=0; mf<2; ++mf)
                    #pragma unroll
                    for (int nf=0; nf<4; ++nf){
                        mma16816(accP[mf][nf], ah[mf], bf[nf]);
                        mma16816(accP[mf][nf], al[mf], bf[nf]);
                    }
                ldB(bofs + 40960u, wn, lane, ks, bf);  // Pl
                #pragma unroll
                for (int mf=0; mf<2; ++mf)
                    #pragma unroll
                    for (int nf=0; nf<4; ++nf)
                        mma16816(accP[mf][nf], ah[mf], bf[nf]);
            }
        }
        __syncthreads();
    }

    if (hasP){
        __nv_bfloat16* dst = ph ? g_bs : g_as;
        int i_idx = t2/6, k0 = (t2%6)*64;
        #pragma unroll
        for (int mf=0; mf<2; ++mf)
            #pragma unroll
            for (int nf=0; nf<4; ++nf){
                int col = wn*32 + nf*8 + (lane&3)*2;
                int row = wm*32 + mf*16 + (lane>>2);
                float mk0 = __ldg(mask_ + t2*64 + row);
                float mk1 = __ldg(mask_ + t2*64 + row + 8);
                float g0=__ldg(GBp+col), g1=__ldg(GBp+col+1);
                float p0=__ldg(PBp+col), p1=__ldg(PBp+col+1);
                ot[col*68+row]       = mk0*sigf(accG[mf][nf][0]+g0)*(accP[mf][nf][0]+p0);
                ot[(col+1)*68+row]   = mk0*sigf(accG[mf][nf][1]+g1)*(accP[mf][nf][1]+p1);
                ot[col*68+row+8]     = mk1*sigf(accG[mf][nf][2]+g0)*(accP[mf][nf][2]+p0);
                ot[(col+1)*68+row+8] = mk1*sigf(accG[mf][nf][3]+g1)*(accP[mf][nf][3]+p1);
            }
        __syncthreads();
        #pragma unroll
        for (int it2=0; it2<32; ++it2){
            int f = tid + it2*256;
            int r = f&63, o = f>>6;
            float v = ot[o*68 + r];
            __nv_bfloat16 hi = __float2bfloat16(v);
            __nv_bfloat16 lo = __float2bfloat16(v - __bfloat162float(hi));
            size_t base = (size_t)o*(NRES*KS2) + (size_t)i_idx*KS2 + (k0 + r);
            dst[base]       = hi;
            dst[base + 384] = lo;
        }
    } else {
        #pragma unroll
        for (int mf=0; mf<2; ++mf)
            #pragma unroll
            for (int nf=0; nf<4; ++nf){
                int col = wn*32 + nf*8 + (lane&3)*2;
                int row = wm*32 + mf*16 + (lane>>2);
                size_t R0 = (size_t)t2*64 + row;
                float g0=__ldg(GBp+col), g1=__ldg(GBp+col+1);
                *(float2*)(g_gate + R0*CH + col) =
                    make_float2(sigf(accG[mf][nf][0]+g0), sigf(accG[mf][nf][1]+g1));
                *(float2*)(g_gate + (R0+8)*CH + col) =
                    make_float2(sigf(accG[mf][nf][2]+g0), sigf(accG[mf][nf][3]+g1));
            }
    }
}

// ================= tri: per (h,i-tile,j-tile) D=A·B^T, 3 terms in-chunk =================
// stage regions: Ah 0, Al 10240, Bh 20480, Bl 30720
#define TSTEP 40960u
#define NCH_T 12

__device__ __forceinline__ void tri_issue(int tid, int c, int buf,
    const __nv_bfloat16* Ag, const __nv_bfloat16* Bg, uint32_t sb){
    int row2 = tid>>2, seg = tid&3;
    uint32_t bofs = (uint32_t)buf*TSTEP;
    #pragma unroll
    for (int it=0; it<2; ++it){
        int row = row2 + it*64;
        uint32_t off = bofs + (uint32_t)(row*80 + seg*16);
        const __nv_bfloat16* ar = Ag + (size_t)row*KS2 + c*BK + seg*8;
        cpa(sb + off,           ar);
        cpa(sb + 10240u + off,  ar+384);
        const __nv_bfloat16* br = Bg + (size_t)row*KS2 + c*BK + seg*8;
        cpa(sb + 20480u + off,  br);
        cpa(sb + 30720u + off,  br+384);
    }
    cp_commit();
}

__global__ __launch_bounds__(256,2)
void tri_mma_kernel(){
    extern __shared__ char sm[];
    uint32_t sb = s2u(sm);

    int tid = threadIdx.x;
    int wid = tid>>5, lane = tid&31;
    int wm = wid & 1, wn = wid >> 1;
    int h = blockIdx.z, i0 = blockIdx.y*128, j0 = blockIdx.x*128;

    const __nv_bfloat16* Ag = g_as + ((size_t)h*NRES + i0)*KS2;
    const __nv_bfloat16* Bg = g_bs + ((size_t)h*NRES + j0)*KS2;

    float acc[4][4][4];
    #pragma unroll
    for (int mf=0;mf<4;++mf)
        #pragma unroll
        for (int nf=0;nf<4;++nf)
            #pragma unroll
            for (int r=0;r<4;++r) acc[mf][nf][r]=0.f;

    tri_issue(tid, 0, 0, Ag, Bg, sb);

    for (int c=0; c<NCH_T; ++c){
        int buf = c & 1;
        if (c+1 < NCH_T){ tri_issue(tid, c+1, buf^1, Ag, Bg, sb); cp_wait<1>(); }
        else cp_wait<0>();
        __syncthreads();
        uint32_t bofs = sb + (uint32_t)buf*TSTEP;
        #pragma unroll
        for (int ks=0; ks<2; ++ks){
            uint32_t ah[4][4];
            #pragma unroll
            for (int mf=0; mf<4; ++mf){
                int row = wm*64 + mf*16 + (lane&15);
                int kc  = ks*16 + (lane>>4)*8;
                ldsm4(ah[mf][0],ah[mf][1],ah[mf][2],ah[mf][3], bofs + (uint32_t)(row*40 + kc)*2);
            }
            uint32_t bf[4][2];
            ldB(bofs + 20480u, wn, lane, ks, bf);   // Bh
            #pragma unroll
            for (int mf=0; mf<4; ++mf)
                #pragma unroll
                for (int nf=0; nf<4; ++nf)
                    mma16816(acc[mf][nf], ah[mf], bf[nf]);
            {
                uint32_t bl[4][2];
                ldB(bofs + 30720u, wn, lane, ks, bl);  // Bl
                #pragma unroll
                for (int mf=0; mf<4; ++mf)
                    #pragma unroll
                    for (int nf=0; nf<4; ++nf)
                        mma16816(acc[mf][nf], ah[mf], bl[nf]);
            }
            #pragma unroll
            for (int mf=0; mf<4; ++mf){   // reuse ah regs for Al
                int row = wm*64 + mf*16 + (lane&15);
                int kc  = ks*16 + (lane>>4)*8;
                ldsm4(ah[mf][0],ah[mf][1],ah[mf][2],ah[mf][3], bofs + 10240u + (uint32_t)(row*40 + kc)*2);
            }
            #pragma unroll
            for (int mf=0; mf<4; ++mf)
                #pragma unroll
                for (int nf=0; nf<4; ++nf)
                    mma16816(acc[mf][nf], ah[mf], bf[nf]);
        }
        __syncthreads();
    }

    float* X = g_xt + (size_t)h*NN;
    #pragma unroll
    for (int mf=0; mf<4; ++mf){
        #pragma unroll
        for (int nf=0; nf<4; ++nf){
            int row = i0 + wm*64 + mf*16 + (lane>>2);
            int col = j0 + wn*32 + nf*8 + (lane&3)*2;
            *(float2*)(X + (size_t)row*NRES + col)     = make_float2(acc[mf][nf][0], acc[mf][nf][1]);
            *(float2*)(X + (size_t)(row+8)*NRES + col) = make_float2(acc[mf][nf][2], acc[mf][nf][3]);
        }
    }
}

// ---- LN over h of x -> split bf16 rows [xh|xl] ----
__global__ __launch_bounds__(256)
void ln_out_split_kernel(const float* __restrict__ low, const float* __restrict__ lob){
    __shared__ float xs[128*66];
    __shared__ float mu_s[64], rs_s[64];
    __shared__ float low_s[128], lob_s[128];
    int tid=threadIdx.x;
    int row0 = blockIdx.x*64;
    if (tid<128){ low_s[tid]=low[tid]; lob_s[tid]=lob[tid]; }
    #pragma unroll
    for (int it=0; it<32; ++it){
        int f = tid + it*256;
        int r = f&63, h = f>>6;
        xs[h*66 + r] = g_xt[(size_t)h*NN + row0 + r];
    }
    __syncthreads();
    int lane=tid&31, wid=tid>>5;
    #pragma unroll
    for (int rr=0;rr<8;++rr){
        int r = wid*8+rr;
        float s=0.f,q=0.f;
        #pragma unroll
        for (int m=0;m<4;++m){ float x=xs[(lane+32*m)*66 + r]; s+=x; q+=x*x; }
        #pragma unroll
        for (int o=16;o>0;o>>=1){ s+=__shfl_xor_sync(0xffffffffu,s,o); q+=__shfl_xor_sync(0xffffffffu,q,o); }
        if (lane==0){
            float mu=s*(1.f/128.f), var=q*(1.f/128.f)-mu*mu;
            mu_s[r]=mu; rs_s[r]=rsqrtf(fmaxf(var,0.f)+EPSF);
        }
    }
    __syncthreads();
    #pragma unroll
    for (int it=0; it<16; ++it){
        int f = tid + it*256;
        int r = f>>6, h2 = (f&63)*2;
        float mu=mu_s[r], rs=rs_s[r];
        float x0 = (xs[(h2+0)*66+r]-mu)*rs*low_s[h2+0]+lob_s[h2+0];
        float x1 = (xs[(h2+1)*66+r]-mu)*rs*low_s[h2+1]+lob_s[h2+1];
        __nv_bfloat16 h0=__float2bfloat16(x0), h1=__float2bfloat16(x1);
        __nv_bfloat16 l0=__float2bfloat16(x0-__bfloat162float(h0));
        __nv_bfloat16 l1=__float2bfloat16(x1-__bfloat162float(h1));
        __nv_bfloat16* d = g_xs + (size_t)(row0+r)*KP2 + h2;
        *(__nv_bfloat162*)(d)     = __nv_bfloat162{h0,h1};
        *(__nv_bfloat162*)(d+128) = __nv_bfloat162{l0,l1};
    }
}

// ================= outmma: out = gate * (xn @ z_w^T + z_b) =================
// stage regions: Xh 0, Xl 5120, Wh 10240, Wl 20480
#define OSTEP 30720u

__device__ __forceinline__ void out_issue(int tid, int c, int buf,
    uint32_t sb, const __nv_bfloat16* Ax, const __nv_bfloat16* W){
    uint32_t bofs = (uint32_t)buf*OSTEP;
    {
        int row = tid>>2, seg = tid&3;
        uint32_t off = bofs + (uint32_t)(row*80 + seg*16);
        const __nv_bfloat16* ar = Ax + (size_t)row*KP2 + c*BK + seg*8;
        cpa(sb + off,          ar);
        cpa(sb + 5120u + off,  ar+128);
    }
    #pragma unroll
    for (int it=0; it<2; ++it){
        int idx = tid + it*256;
        int row = idx>>2, seg = idx&3;
        uint32_t off = bofs + (uint32_t)(row*80 + seg*16);
        const __nv_bfloat16* wr = W + (size_t)row*KP2 + c*BK + seg*8;
        cpa(sb + 10240u + off, wr);
        cpa(sb + 20480u + off, wr+128);
    }
    cp_commit();
}

__global__ __launch_bounds__(256,2)
void outmma_kernel(const float* __restrict__ zb, float* __restrict__ out)
{
    extern __shared__ char sm[];
    uint32_t sb = s2u(sm);

    int tid=threadIdx.x, wid=tid>>5, lane=tid&31;
    int wm=wid&1, wn=wid>>1;
    int t2 = blockIdx.x;
    const __nv_bfloat16* W = g_ws + (size_t)5*CH*KP2;
    const __nv_bfloat16* Ax = g_xs + (size_t)t2*64*KP2;

    float acc[2][4][4];
    #pragma unroll
    for (int mf=0;mf<2;++mf)
        #pragma unroll
        for (int nf=0;nf<4;++nf)
            #pragma unroll
            for (int r=0;r<4;++r) acc[mf][nf][r]=0.f;

    out_issue(tid, 0, 0, sb, Ax, W);

    for (int c=0; c<NCH_P; ++c){
        int buf = c & 1;
        if (c+1<NCH_P){ out_issue(tid, c+1, buf^1, sb, Ax, W); cp_wait<1>(); }
        else cp_wait<0>();
        __syncthreads();
        uint32_t bofs = sb + (uint32_t)buf*OSTEP;
        #pragma unroll
        for (int ks=0; ks<2; ++ks){
            uint32_t ah[2][4], al[2][4];
            #pragma unroll
            for (int mf=0; mf<2; ++mf){
                int row = wm*32 + mf*16 + (lane&15);
                int kc  = ks*16 + (lane>>4)*8;
                uint32_t ro = (uint32_t)(row*40 + kc)*2;
                ldsm4(ah[mf][0],ah[mf][1],ah[mf][2],ah[mf][3], bofs + ro);
                ldsm4(al[mf][0],al[mf][1],al[mf][2],al[mf][3], bofs + 5120u + ro);
            }
            uint32_t bf[4][2];
            ldB(bofs + 10240u, wn, lane, ks, bf);   // Wh
            #pragma unroll
            for (int mf=0; mf<2; ++mf)
                #pragma unroll
                for (int nf=0; nf<4; ++nf){
                    mma16816(acc[mf][nf], ah[mf], bf[nf]);
                    mma16816(acc[mf][nf], al[mf], bf[nf]);
                }
            ldB(bofs + 20480u, wn, lane, ks, bf);   // Wl
            #pragma unroll
            for (int mf=0; mf<2; ++mf)
                #pragma unroll
                for (int nf=0; nf<4; ++nf)
                    mma16816(acc[mf][nf], ah[mf], bf[nf]);
        }
        __syncthreads();
    }

    #pragma unroll
    for (int mf=0; mf<2; ++mf)
        #pragma unroll
        for (int nf=0; nf<4; ++nf){
            int col = wn*32 + nf*8 + (lane&3)*2;
            int row = wm*32 + mf*16 + (lane>>2);
            size_t R0 = (size_t)t2*64 + row;
            float2 zb2 = *(const float2*)(zb + col);
            float2 ga = *(const float2*)(g_gate + R0*CH + col);
            float2 gb2 = *(const float2*)(g_gate + (R0+8)*CH + col);
            *(float2*)(out + R0*CH + col) =
                make_float2(ga.x*(acc[mf][nf][0]+zb2.x), ga.y*(acc[mf][nf][1]+zb2.y));
            *(float2*)(out + (R0+8)*CH + col) =
                make_float2(gb2.x*(acc[mf][nf][2]+zb2.x), gb2.y*(acc[mf][nf][3]+zb2.y));
        }
}

extern "C" void kernel_launch(void* const* d_in, const int* in_sizes, int n_in,
                              void* d_out, int out_size) {
    const float* z      = (const float*)d_in[0];
    const float* mask   = (const float*)d_in[1];
    const float* ln_in_w= (const float*)d_in[2];
    const float* ln_in_b= (const float*)d_in[3];
    const float* a_g_w  = (const float*)d_in[4];
    const float* a_g_b  = (const float*)d_in[5];
    const float* a_p_w  = (const float*)d_in[6];
    const float* a_p_b  = (const float*)d_in[7];
    const float* b_g_w  = (const float*)d_in[8];
    const float* b_g_b  = (const float*)d_in[9];
    const float* b_p_w  = (const float*)d_in[10];
    const float* b_p_b  = (const float*)d_in[11];
    const float* g_w    = (const float*)d_in[12];
    const float* g_b    = (const float*)d_in[13];
    const float* ln_out_w=(const float*)d_in[14];
    const float* ln_out_b=(const float*)d_in[15];
    const float* z_w    = (const float*)d_in[16];
    const float* z_b    = (const float*)d_in[17];
    float* out = (float*)d_out;

    cudaFuncSetAttribute(projmma_kernel, cudaFuncAttributeMaxDynamicSharedMemorySize, 2*PSTEP);
    cudaFuncSetAttribute(tri_mma_kernel, cudaFuncAttributeMaxDynamicSharedMemorySize, 2*TSTEP);
    cudaFuncSetAttribute(outmma_kernel, cudaFuncAttributeMaxDynamicSharedMemorySize, 2*OSTEP);

    wsplit_kernel<<<6,256>>>(a_g_w, a_p_w, b_g_w, b_p_w, g_w, z_w);
    ln_split_kernel<<<NN/8,256>>>(z, ln_in_w, ln_in_b);
    projmma_kernel<<<dim3(2304,3),256,2*PSTEP>>>(mask, a_g_b, a_p_b, b_g_b, b_p_b, g_b);
    tri_mma_kernel<<<dim3(3,3,CH),256,2*TSTEP>>>();
    ln_out_split_kernel<<<NN/64,256>>>(ln_out_w, ln_out_b);
    outmma_kernel<<<NN/64,256,2*OSTEP>>>(z_b, out);
}